// round 2
// baseline (speedup 1.0000x reference)
#include <cuda_runtime.h>
#include <math.h>

#define DM    1024
#define DFF   4096
#define NH    16
#define DH    64
#define BATCH 2
#define SEQ   2048
#define MTOK  (BATCH*SEQ)   // 4096 tokens
#define EPSLN 1e-5f

// ---------------- scratch (device globals; no allocation allowed) ----------
__device__ float gQ [MTOK*DM];
__device__ float gK [MTOK*DM];
__device__ float gV [MTOK*DM];
__device__ float gA [MTOK*DM];   // attention output (concat heads)
__device__ float gP [MTOK*DM];   // attn out-proj
__device__ float gH [MTOK*DM];   // after LN1
__device__ float gF1[MTOK*DFF];  // FFN hidden
__device__ float gF2[MTOK*DM];   // FFN out

// ---------------- SGEMM: C[M,N] = A[M,K] @ W[N,K]^T + bias, opt ReLU -------
#define BM 128
#define BN 128
#define BK 16
#define TM 8
#define TN 8

__global__ void __launch_bounds__(256) sgemm_bias(
    const float* __restrict__ A, const float* __restrict__ W,
    const float* __restrict__ bias, float* __restrict__ C,
    int M, int N, int K, int doRelu)
{
    __shared__ float As[BK][BM];
    __shared__ float Bs[BK][BN];

    const int tid = threadIdx.x;
    const int bm  = blockIdx.y * BM;
    const int bn  = blockIdx.x * BN;
    const int tx  = tid & 15;        // 0..15  (N dir)
    const int ty  = tid >> 4;        // 0..15  (M dir)

    const int lr = tid >> 2;         // 0..63  load row
    const int lc = (tid & 3) * 4;    // 0,4,8,12 k-offset

    float acc[TM][TN];
    #pragma unroll
    for (int i = 0; i < TM; i++)
        #pragma unroll
        for (int j = 0; j < TN; j++) acc[i][j] = 0.f;

    for (int k0 = 0; k0 < K; k0 += BK) {
        #pragma unroll
        for (int r = 0; r < 2; r++) {
            int row = lr + r * 64;
            float4 a = *(const float4*)&A[(size_t)(bm + row) * K + k0 + lc];
            As[lc+0][row] = a.x; As[lc+1][row] = a.y;
            As[lc+2][row] = a.z; As[lc+3][row] = a.w;
            float4 b = *(const float4*)&W[(size_t)(bn + row) * K + k0 + lc];
            Bs[lc+0][row] = b.x; Bs[lc+1][row] = b.y;
            Bs[lc+2][row] = b.z; Bs[lc+3][row] = b.w;
        }
        __syncthreads();

        #pragma unroll
        for (int k = 0; k < BK; k++) {
            float ra[TM], rb[TN];
            #pragma unroll
            for (int i = 0; i < TM; i++) ra[i] = As[k][ty*TM + i];
            #pragma unroll
            for (int j = 0; j < TN; j++) rb[j] = Bs[k][tx*TN + j];
            #pragma unroll
            for (int i = 0; i < TM; i++)
                #pragma unroll
                for (int j = 0; j < TN; j++)
                    acc[i][j] += ra[i] * rb[j];
        }
        __syncthreads();
    }

    #pragma unroll
    for (int i = 0; i < TM; i++) {
        int row = bm + ty*TM + i;
        #pragma unroll
        for (int j = 0; j < TN; j += 4) {
            int col = bn + tx*TN + j;
            float4 o;
            o.x = acc[i][j+0] + bias[col+0];
            o.y = acc[i][j+1] + bias[col+1];
            o.z = acc[i][j+2] + bias[col+2];
            o.w = acc[i][j+3] + bias[col+3];
            if (doRelu) {
                o.x = fmaxf(o.x, 0.f); o.y = fmaxf(o.y, 0.f);
                o.z = fmaxf(o.z, 0.f); o.w = fmaxf(o.w, 0.f);
            }
            *(float4*)&C[(size_t)row * N + col] = o;
        }
    }
}

// ---------------- Flash-style attention (fp32, online softmax) -------------
// grid: (SEQ/128, NH, BATCH), block: 128 threads, 1 q-row per thread.
#define AKT 64

__global__ void __launch_bounds__(128) attn_kernel(
    const float* __restrict__ Q, const float* __restrict__ K,
    const float* __restrict__ V, float* __restrict__ O)
{
    const int h = blockIdx.y;
    const int b = blockIdx.z;
    const int qrow = b * SEQ + blockIdx.x * 128 + threadIdx.x;

    const float* qp = Q + (size_t)qrow * DM + h * DH;
    float q[DH], o[DH];
    #pragma unroll
    for (int j = 0; j < DH; j += 4) {
        float4 t = *(const float4*)&qp[j];
        q[j] = t.x; q[j+1] = t.y; q[j+2] = t.z; q[j+3] = t.w;
        o[j] = 0.f; o[j+1] = 0.f; o[j+2] = 0.f; o[j+3] = 0.f;
    }
    float m = -INFINITY, l = 0.f;

    __shared__ float Ks[AKT][DH];
    __shared__ float Vs[AKT][DH];

    for (int kt = 0; kt < SEQ; kt += AKT) {
        __syncthreads();
        // load K/V tile: AKT*DH/4 = 1024 float4s, 128 threads -> 8 each
        for (int i = threadIdx.x; i < AKT * DH / 4; i += 128) {
            int r = i >> 4;            // 0..63
            int c = (i & 15) * 4;      // 0..60
            int krow = b * SEQ + kt + r;
            *(float4*)&Ks[r][c] = *(const float4*)&K[(size_t)krow * DM + h * DH + c];
            *(float4*)&Vs[r][c] = *(const float4*)&V[(size_t)krow * DM + h * DH + c];
        }
        __syncthreads();

        for (int kk = 0; kk < AKT; kk++) {
            float s = 0.f;
            #pragma unroll
            for (int j = 0; j < DH; j += 4) {
                float4 kv = *(const float4*)&Ks[kk][j];
                s += q[j]*kv.x + q[j+1]*kv.y + q[j+2]*kv.z + q[j+3]*kv.w;
            }
            s *= 0.125f;  // 1/sqrt(64)
            float mnew  = fmaxf(m, s);
            float scale = __expf(m - mnew);
            float p     = __expf(s - mnew);
            l = l * scale + p;
            m = mnew;
            #pragma unroll
            for (int j = 0; j < DH; j += 4) {
                float4 vv = *(const float4*)&Vs[kk][j];
                o[j]   = o[j]  *scale + p*vv.x;
                o[j+1] = o[j+1]*scale + p*vv.y;
                o[j+2] = o[j+2]*scale + p*vv.z;
                o[j+3] = o[j+3]*scale + p*vv.w;
            }
        }
    }

    const float inv = 1.f / l;
    float* op = O + (size_t)qrow * DM + h * DH;
    #pragma unroll
    for (int j = 0; j < DH; j += 4) {
        float4 t;
        t.x = o[j]*inv; t.y = o[j+1]*inv; t.z = o[j+2]*inv; t.w = o[j+3]*inv;
        *(float4*)&op[j] = t;
    }
}

// ---------------- residual add + LayerNorm ---------------------------------
// one block (256 thr) per row of 1024; each thread owns 4 elements.
__global__ void __launch_bounds__(256) add_ln_kernel(
    const float* __restrict__ A, const float* __restrict__ B,
    const float* __restrict__ g, const float* __restrict__ be,
    float* __restrict__ out)
{
    const int row = blockIdx.x;
    const int c   = threadIdx.x * 4;

    float4 a = *(const float4*)&A[(size_t)row * DM + c];
    float4 b = *(const float4*)&B[(size_t)row * DM + c];
    float v0 = a.x + b.x, v1 = a.y + b.y, v2 = a.z + b.z, v3 = a.w + b.w;

    float s  = v0 + v1 + v2 + v3;
    float ss = v0*v0 + v1*v1 + v2*v2 + v3*v3;

    #pragma unroll
    for (int off = 16; off > 0; off >>= 1) {
        s  += __shfl_xor_sync(0xffffffffu, s,  off);
        ss += __shfl_xor_sync(0xffffffffu, ss, off);
    }
    __shared__ float rs[8], rss[8];
    const int warp = threadIdx.x >> 5, lane = threadIdx.x & 31;
    if (lane == 0) { rs[warp] = s; rss[warp] = ss; }
    __syncthreads();
    float st = 0.f, sst = 0.f;
    #pragma unroll
    for (int w = 0; w < 8; w++) { st += rs[w]; sst += rss[w]; }

    const float mu   = st  * (1.f / DM);
    const float var  = sst * (1.f / DM) - mu * mu;
    const float rstd = rsqrtf(var + EPSLN);

    float4 gg = *(const float4*)&g[c];
    float4 bb = *(const float4*)&be[c];
    float4 o;
    o.x = (v0 - mu) * rstd * gg.x + bb.x;
    o.y = (v1 - mu) * rstd * gg.y + bb.y;
    o.z = (v2 - mu) * rstd * gg.z + bb.z;
    o.w = (v3 - mu) * rstd * gg.w + bb.w;
    *(float4*)&out[(size_t)row * DM + c] = o;
}

// ---------------- launch ----------------------------------------------------
extern "C" void kernel_launch(void* const* d_in, const int* in_sizes, int n_in,
                              void* d_out, int out_size)
{
    const float* x   = (const float*)d_in[0];
    const float* Wq  = (const float*)d_in[1];
    const float* bq  = (const float*)d_in[2];
    const float* Wk  = (const float*)d_in[3];
    const float* bk  = (const float*)d_in[4];
    const float* Wv  = (const float*)d_in[5];
    const float* bv  = (const float*)d_in[6];
    const float* Wo  = (const float*)d_in[7];
    const float* bo  = (const float*)d_in[8];
    const float* W1  = (const float*)d_in[9];
    const float* b1  = (const float*)d_in[10];
    const float* W2  = (const float*)d_in[11];
    const float* b2  = (const float*)d_in[12];
    const float* g1  = (const float*)d_in[13];
    const float* be1 = (const float*)d_in[14];
    const float* g2  = (const float*)d_in[15];
    const float* be2 = (const float*)d_in[16];
    float* out = (float*)d_out;

    float *q, *k, *v, *a, *p, *h, *f1, *f2;
    cudaGetSymbolAddress((void**)&q,  gQ);
    cudaGetSymbolAddress((void**)&k,  gK);
    cudaGetSymbolAddress((void**)&v,  gV);
    cudaGetSymbolAddress((void**)&a,  gA);
    cudaGetSymbolAddress((void**)&p,  gP);
    cudaGetSymbolAddress((void**)&h,  gH);
    cudaGetSymbolAddress((void**)&f1, gF1);
    cudaGetSymbolAddress((void**)&f2, gF2);

    dim3 gProj(DM / BN, MTOK / BM);    // (8, 32)
    dim3 gFF1 (DFF / BN, MTOK / BM);   // (32, 32)

    sgemm_bias<<<gProj, 256>>>(x, Wq, bq, q, MTOK, DM, DM, 0);
    sgemm_bias<<<gProj, 256>>>(x, Wk, bk, k, MTOK, DM, DM, 0);
    sgemm_bias<<<gProj, 256>>>(x, Wv, bv, v, MTOK, DM, DM, 0);

    attn_kernel<<<dim3(SEQ / 128, NH, BATCH), 128>>>(q, k, v, a);

    sgemm_bias<<<gProj, 256>>>(a, Wo, bo, p, MTOK, DM, DM, 0);
    add_ln_kernel<<<MTOK, 256>>>(x, p, g1, be1, h);

    sgemm_bias<<<gFF1, 256>>>(h, W1, b1, f1, MTOK, DFF, DM, 1);
    sgemm_bias<<<gProj, 256>>>(f1, W2, b2, f2, MTOK, DM, DFF, 0);
    add_ln_kernel<<<MTOK, 256>>>(h, f2, g2, be2, out);
}

// round 4
// speedup vs baseline: 2.9722x; 2.9722x over previous
#include <cuda_runtime.h>
#include <cstdint>
#include <math.h>

#define DM    1024
#define DFF   4096
#define NH    16
#define DH    64
#define BATCH 2
#define SEQ   2048
#define MTOK  (BATCH*SEQ)   // 4096 tokens
#define EPSLN 1e-5f

// ---------------- scratch (device globals; no allocation allowed) ----------
__device__ float gQ [MTOK*DM];
__device__ float gK [MTOK*DM];
__device__ float gV [MTOK*DM];
__device__ float gA [MTOK*DM];   // attention output (concat heads)
__device__ float gP [MTOK*DM];   // attn out-proj
__device__ float gH [MTOK*DM];   // after LN1
__device__ float gF1[MTOK*DFF];  // FFN hidden
__device__ float gF2[MTOK*DM];   // FFN out

// ======================= helpers ===========================================
__device__ __forceinline__ uint32_t f2tf32(float f) {
    uint32_t r;
    asm("cvt.rna.tf32.f32 %0, %1;" : "=r"(r) : "f"(f));
    return r;
}

// warp-level tf32 MMA: D(16x8) += A(16x8) * B(8x8); valid PTX for sm_80+.
__device__ __forceinline__ void mma16n8k8(float* c, const uint32_t* a, const uint32_t* b) {
    asm volatile(
        "mma.sync.aligned.m16n8k8.row.col.f32.tf32.tf32.f32 "
        "{%0,%1,%2,%3}, {%4,%5,%6,%7}, {%8,%9}, {%0,%1,%2,%3};"
        : "+f"(c[0]), "+f"(c[1]), "+f"(c[2]), "+f"(c[3])
        : "r"(a[0]), "r"(a[1]), "r"(a[2]), "r"(a[3]), "r"(b[0]), "r"(b[1]));
}

// ======================= tf32 mma.sync GEMM ================================
// C[M,N] = A[M,K] @ W[N,K]^T + bias, optional ReLU.
// Block 128x128, 256 threads = 8 warps (2 M x 4 N), warp tile 64x32.
// smem: As[128][36], Bs[128][36] (row-major, pad 4 -> conflict-free frag LDS).
#define GBM 128
#define GBN 128
#define GBK 32
#define LDA 36

__global__ void __launch_bounds__(256, 2) tc_gemm(
    const float* __restrict__ A, const float* __restrict__ W,
    const float* __restrict__ bias, float* __restrict__ C,
    int M, int N, int K, int doRelu)
{
    __shared__ float As[GBM * LDA];
    __shared__ float Bs[GBN * LDA];

    const int tid  = threadIdx.x;
    const int wid  = tid >> 5;
    const int lane = tid & 31;
    const int g    = lane >> 2;   // 0..7  (row group)
    const int r    = lane & 3;    // 0..3  (k offset)
    const int warpM = wid >> 2;   // 0..1
    const int warpN = wid & 3;    // 0..3

    const int bm = blockIdx.y * GBM;
    const int bn = blockIdx.x * GBN;

    // gmem load mapping: 1024 float4 per tile, 4 per thread
    const int lrow = tid >> 3;          // 0..31 base row (+32 per rep)
    const int lcq  = (tid & 7) * 4;     // 0,4,...,28

    float acc[4][4][4];
    #pragma unroll
    for (int mi = 0; mi < 4; mi++)
        #pragma unroll
        for (int ni = 0; ni < 4; ni++)
            #pragma unroll
            for (int j = 0; j < 4; j++) acc[mi][ni][j] = 0.f;

    for (int k0 = 0; k0 < K; k0 += GBK) {
        __syncthreads();
        #pragma unroll
        for (int rep = 0; rep < 4; rep++) {
            int row = lrow + rep * 32;
            float4 a = *(const float4*)&A[(size_t)(bm + row) * K + k0 + lcq];
            uint4 ta = make_uint4(f2tf32(a.x), f2tf32(a.y), f2tf32(a.z), f2tf32(a.w));
            *(uint4*)&As[row * LDA + lcq] = ta;
            float4 b = *(const float4*)&W[(size_t)(bn + row) * K + k0 + lcq];
            uint4 tb = make_uint4(f2tf32(b.x), f2tf32(b.y), f2tf32(b.z), f2tf32(b.w));
            *(uint4*)&Bs[row * LDA + lcq] = tb;
        }
        __syncthreads();

        #pragma unroll
        for (int kt = 0; kt < GBK; kt += 8) {
            uint32_t af[4][4], bf[4][2];
            #pragma unroll
            for (int mi = 0; mi < 4; mi++) {
                int m0 = warpM * 64 + mi * 16;
                af[mi][0] = __float_as_uint(As[(m0 + g)     * LDA + kt + r]);
                af[mi][1] = __float_as_uint(As[(m0 + 8 + g) * LDA + kt + r]);
                af[mi][2] = __float_as_uint(As[(m0 + g)     * LDA + kt + 4 + r]);
                af[mi][3] = __float_as_uint(As[(m0 + 8 + g) * LDA + kt + 4 + r]);
            }
            #pragma unroll
            for (int ni = 0; ni < 4; ni++) {
                int n0 = warpN * 32 + ni * 8;
                bf[ni][0] = __float_as_uint(Bs[(n0 + g) * LDA + kt + r]);
                bf[ni][1] = __float_as_uint(Bs[(n0 + g) * LDA + kt + 4 + r]);
            }
            #pragma unroll
            for (int mi = 0; mi < 4; mi++)
                #pragma unroll
                for (int ni = 0; ni < 4; ni++)
                    mma16n8k8(acc[mi][ni], af[mi], bf[ni]);
        }
    }

    // epilogue: bias (+ReLU), direct STG
    #pragma unroll
    for (int ni = 0; ni < 4; ni++) {
        int col = bn + warpN * 32 + ni * 8 + 2 * r;
        float bx = bias[col], by = bias[col + 1];
        #pragma unroll
        for (int mi = 0; mi < 4; mi++) {
            int row0 = bm + warpM * 64 + mi * 16 + g;
            float2 v0, v1;
            v0.x = acc[mi][ni][0] + bx; v0.y = acc[mi][ni][1] + by;
            v1.x = acc[mi][ni][2] + bx; v1.y = acc[mi][ni][3] + by;
            if (doRelu) {
                v0.x = fmaxf(v0.x, 0.f); v0.y = fmaxf(v0.y, 0.f);
                v1.x = fmaxf(v1.x, 0.f); v1.y = fmaxf(v1.y, 0.f);
            }
            *(float2*)&C[(size_t)row0 * N + col]       = v0;
            *(float2*)&C[(size_t)(row0 + 8) * N + col] = v1;
        }
    }
}

// ---------------- Flash-style attention (fp32, online softmax) -------------
// grid: (SEQ/128, NH, BATCH), block: 128 threads, 1 q-row per thread.
#define AKT 64

__global__ void __launch_bounds__(128) attn_kernel(
    const float* __restrict__ Q, const float* __restrict__ K,
    const float* __restrict__ V, float* __restrict__ O)
{
    const int h = blockIdx.y;
    const int b = blockIdx.z;
    const int qrow = b * SEQ + blockIdx.x * 128 + threadIdx.x;

    const float* qp = Q + (size_t)qrow * DM + h * DH;
    float q[DH], o[DH];
    #pragma unroll
    for (int j = 0; j < DH; j += 4) {
        float4 t = *(const float4*)&qp[j];
        q[j]   = t.x * 0.125f; q[j+1] = t.y * 0.125f;
        q[j+2] = t.z * 0.125f; q[j+3] = t.w * 0.125f;
        o[j] = 0.f; o[j+1] = 0.f; o[j+2] = 0.f; o[j+3] = 0.f;
    }
    float m = -INFINITY, l = 0.f;

    __shared__ float Ks[AKT][DH];
    __shared__ float Vs[AKT][DH];

    for (int kt = 0; kt < SEQ; kt += AKT) {
        __syncthreads();
        for (int i = threadIdx.x; i < AKT * DH / 4; i += 128) {
            int r = i >> 4;
            int c = (i & 15) * 4;
            int krow = b * SEQ + kt + r;
            *(float4*)&Ks[r][c] = *(const float4*)&K[(size_t)krow * DM + h * DH + c];
            *(float4*)&Vs[r][c] = *(const float4*)&V[(size_t)krow * DM + h * DH + c];
        }
        __syncthreads();

        for (int kk = 0; kk < AKT; kk++) {
            float s = 0.f;
            #pragma unroll
            for (int j = 0; j < DH; j += 4) {
                float4 kv = *(const float4*)&Ks[kk][j];
                s += q[j]*kv.x + q[j+1]*kv.y + q[j+2]*kv.z + q[j+3]*kv.w;
            }
            if (s > m) {
                // new running max: rescale (rare after warm-up); p = 1 here
                float scale = __expf(m - s);
                m = s;
                l = l * scale + 1.f;
                #pragma unroll
                for (int j = 0; j < DH; j += 4) {
                    float4 vv = *(const float4*)&Vs[kk][j];
                    o[j]   = o[j]  *scale + vv.x;
                    o[j+1] = o[j+1]*scale + vv.y;
                    o[j+2] = o[j+2]*scale + vv.z;
                    o[j+3] = o[j+3]*scale + vv.w;
                }
            } else {
                float p = __expf(s - m);
                l += p;
                #pragma unroll
                for (int j = 0; j < DH; j += 4) {
                    float4 vv = *(const float4*)&Vs[kk][j];
                    o[j]   += p*vv.x;
                    o[j+1] += p*vv.y;
                    o[j+2] += p*vv.z;
                    o[j+3] += p*vv.w;
                }
            }
        }
    }

    const float inv = 1.f / l;
    float* op = O + (size_t)qrow * DM + h * DH;
    #pragma unroll
    for (int j = 0; j < DH; j += 4) {
        float4 t;
        t.x = o[j]*inv; t.y = o[j+1]*inv; t.z = o[j+2]*inv; t.w = o[j+3]*inv;
        *(float4*)&op[j] = t;
    }
}

// ---------------- residual add + LayerNorm ---------------------------------
__global__ void __launch_bounds__(256) add_ln_kernel(
    const float* __restrict__ A, const float* __restrict__ B,
    const float* __restrict__ g, const float* __restrict__ be,
    float* __restrict__ out)
{
    const int row = blockIdx.x;
    const int c   = threadIdx.x * 4;

    float4 a = *(const float4*)&A[(size_t)row * DM + c];
    float4 b = *(const float4*)&B[(size_t)row * DM + c];
    float v0 = a.x + b.x, v1 = a.y + b.y, v2 = a.z + b.z, v3 = a.w + b.w;

    float s  = v0 + v1 + v2 + v3;
    float ss = v0*v0 + v1*v1 + v2*v2 + v3*v3;

    #pragma unroll
    for (int off = 16; off > 0; off >>= 1) {
        s  += __shfl_xor_sync(0xffffffffu, s,  off);
        ss += __shfl_xor_sync(0xffffffffu, ss, off);
    }
    __shared__ float rs[8], rss[8];
    const int warp = threadIdx.x >> 5, lane = threadIdx.x & 31;
    if (lane == 0) { rs[warp] = s; rss[warp] = ss; }
    __syncthreads();
    float st = 0.f, sst = 0.f;
    #pragma unroll
    for (int w = 0; w < 8; w++) { st += rs[w]; sst += rss[w]; }

    const float mu   = st  * (1.f / DM);
    const float var  = sst * (1.f / DM) - mu * mu;
    const float rstd = rsqrtf(var + EPSLN);

    float4 gg = *(const float4*)&g[c];
    float4 bb = *(const float4*)&be[c];
    float4 o;
    o.x = (v0 - mu) * rstd * gg.x + bb.x;
    o.y = (v1 - mu) * rstd * gg.y + bb.y;
    o.z = (v2 - mu) * rstd * gg.z + bb.z;
    o.w = (v3 - mu) * rstd * gg.w + bb.w;
    *(float4*)&out[(size_t)row * DM + c] = o;
}

// ---------------- launch ----------------------------------------------------
extern "C" void kernel_launch(void* const* d_in, const int* in_sizes, int n_in,
                              void* d_out, int out_size)
{
    const float* x   = (const float*)d_in[0];
    const float* Wq  = (const float*)d_in[1];
    const float* bq  = (const float*)d_in[2];
    const float* Wk  = (const float*)d_in[3];
    const float* bk  = (const float*)d_in[4];
    const float* Wv  = (const float*)d_in[5];
    const float* bv  = (const float*)d_in[6];
    const float* Wo  = (const float*)d_in[7];
    const float* bo  = (const float*)d_in[8];
    const float* W1  = (const float*)d_in[9];
    const float* b1  = (const float*)d_in[10];
    const float* W2  = (const float*)d_in[11];
    const float* b2  = (const float*)d_in[12];
    const float* g1  = (const float*)d_in[13];
    const float* be1 = (const float*)d_in[14];
    const float* g2  = (const float*)d_in[15];
    const float* be2 = (const float*)d_in[16];
    float* out = (float*)d_out;

    float *q, *k, *v, *a, *p, *h, *f1, *f2;
    cudaGetSymbolAddress((void**)&q,  gQ);
    cudaGetSymbolAddress((void**)&k,  gK);
    cudaGetSymbolAddress((void**)&v,  gV);
    cudaGetSymbolAddress((void**)&a,  gA);
    cudaGetSymbolAddress((void**)&p,  gP);
    cudaGetSymbolAddress((void**)&h,  gH);
    cudaGetSymbolAddress((void**)&f1, gF1);
    cudaGetSymbolAddress((void**)&f2, gF2);

    dim3 gProj(DM / GBN,  MTOK / GBM);   // (8, 32)
    dim3 gFF1 (DFF / GBN, MTOK / GBM);   // (32, 32)

    tc_gemm<<<gProj, 256>>>(x, Wq, bq, q, MTOK, DM, DM, 0);
    tc_gemm<<<gProj, 256>>>(x, Wk, bk, k, MTOK, DM, DM, 0);
    tc_gemm<<<gProj, 256>>>(x, Wv, bv, v, MTOK, DM, DM, 0);

    attn_kernel<<<dim3(SEQ / 128, NH, BATCH), 128>>>(q, k, v, a);

    tc_gemm<<<gProj, 256>>>(a, Wo, bo, p, MTOK, DM, DM, 0);
    add_ln_kernel<<<MTOK, 256>>>(x, p, g1, be1, h);

    tc_gemm<<<gFF1, 256>>>(h, W1, b1, f1, MTOK, DFF, DM, 1);
    tc_gemm<<<gProj, 256>>>(f1, W2, b2, f2, MTOK, DM, DFF, 0);
    add_ln_kernel<<<MTOK, 256>>>(h, f2, g2, be2, out);
}

// round 6
// speedup vs baseline: 3.8145x; 1.2834x over previous
#include <cuda_runtime.h>
#include <cstdint>
#include <math.h>

#define DM    1024
#define DFF   4096
#define NH    16
#define DH    64
#define BATCH 2
#define SEQ   2048
#define MTOK  (BATCH*SEQ)   // 4096 tokens
#define EPSLN 1e-5f

// ---------------- scratch (device globals; no allocation allowed) ----------
__device__ float gQ [MTOK*DM];
__device__ float gK [MTOK*DM];
__device__ float gV [MTOK*DM];
__device__ float gA [MTOK*DM];   // attention output (concat heads)
__device__ float gP [MTOK*DM];   // attn out-proj
__device__ float gH [MTOK*DM];   // after LN1
__device__ float gF1[MTOK*DFF];  // FFN hidden
__device__ float gF2[MTOK*DM];   // FFN out

// ======================= helpers ===========================================
__device__ __forceinline__ uint32_t f2tf32(float f) {
    uint32_t r;
    asm("cvt.rna.tf32.f32 %0, %1;" : "=r"(r) : "f"(f));
    return r;
}

// warp-level tf32 MMA: D(16x8) += A(16x8) * B(8x8); valid PTX for sm_80+.
__device__ __forceinline__ void mma16n8k8(float* c, const uint32_t* a, const uint32_t* b) {
    asm volatile(
        "mma.sync.aligned.m16n8k8.row.col.f32.tf32.tf32.f32 "
        "{%0,%1,%2,%3}, {%4,%5,%6,%7}, {%8,%9}, {%0,%1,%2,%3};"
        : "+f"(c[0]), "+f"(c[1]), "+f"(c[2]), "+f"(c[3])
        : "r"(a[0]), "r"(a[1]), "r"(a[2]), "r"(a[3]), "r"(b[0]), "r"(b[1]));
}

// ======================= tf32 mma.sync GEMM ================================
// C[M,N] = A[M,K] @ W[N,K]^T + bias, optional ReLU.
// Block 128x128, 256 threads = 8 warps (2 M x 4 N), warp tile 64x32.
#define GBM 128
#define GBN 128
#define GBK 32
#define LDA 36

__global__ void __launch_bounds__(256, 2) tc_gemm(
    const float* __restrict__ A, const float* __restrict__ W,
    const float* __restrict__ bias, float* __restrict__ C,
    int M, int N, int K, int doRelu)
{
    __shared__ float As[GBM * LDA];
    __shared__ float Bs[GBN * LDA];

    const int tid  = threadIdx.x;
    const int wid  = tid >> 5;
    const int lane = tid & 31;
    const int g    = lane >> 2;
    const int r    = lane & 3;
    const int warpM = wid >> 2;
    const int warpN = wid & 3;

    const int bm = blockIdx.y * GBM;
    const int bn = blockIdx.x * GBN;

    const int lrow = tid >> 3;
    const int lcq  = (tid & 7) * 4;

    float acc[4][4][4];
    #pragma unroll
    for (int mi = 0; mi < 4; mi++)
        #pragma unroll
        for (int ni = 0; ni < 4; ni++)
            #pragma unroll
            for (int j = 0; j < 4; j++) acc[mi][ni][j] = 0.f;

    for (int k0 = 0; k0 < K; k0 += GBK) {
        __syncthreads();
        #pragma unroll
        for (int rep = 0; rep < 4; rep++) {
            int row = lrow + rep * 32;
            float4 a = *(const float4*)&A[(size_t)(bm + row) * K + k0 + lcq];
            uint4 ta = make_uint4(f2tf32(a.x), f2tf32(a.y), f2tf32(a.z), f2tf32(a.w));
            *(uint4*)&As[row * LDA + lcq] = ta;
            float4 b = *(const float4*)&W[(size_t)(bn + row) * K + k0 + lcq];
            uint4 tb = make_uint4(f2tf32(b.x), f2tf32(b.y), f2tf32(b.z), f2tf32(b.w));
            *(uint4*)&Bs[row * LDA + lcq] = tb;
        }
        __syncthreads();

        #pragma unroll
        for (int kt = 0; kt < GBK; kt += 8) {
            uint32_t af[4][4], bf[4][2];
            #pragma unroll
            for (int mi = 0; mi < 4; mi++) {
                int m0 = warpM * 64 + mi * 16;
                af[mi][0] = __float_as_uint(As[(m0 + g)     * LDA + kt + r]);
                af[mi][1] = __float_as_uint(As[(m0 + 8 + g) * LDA + kt + r]);
                af[mi][2] = __float_as_uint(As[(m0 + g)     * LDA + kt + 4 + r]);
                af[mi][3] = __float_as_uint(As[(m0 + 8 + g) * LDA + kt + 4 + r]);
            }
            #pragma unroll
            for (int ni = 0; ni < 4; ni++) {
                int n0 = warpN * 32 + ni * 8;
                bf[ni][0] = __float_as_uint(Bs[(n0 + g) * LDA + kt + r]);
                bf[ni][1] = __float_as_uint(Bs[(n0 + g) * LDA + kt + 4 + r]);
            }
            #pragma unroll
            for (int mi = 0; mi < 4; mi++)
                #pragma unroll
                for (int ni = 0; ni < 4; ni++)
                    mma16n8k8(acc[mi][ni], af[mi], bf[ni]);
        }
    }

    #pragma unroll
    for (int ni = 0; ni < 4; ni++) {
        int col = bn + warpN * 32 + ni * 8 + 2 * r;
        float bx = bias[col], by = bias[col + 1];
        #pragma unroll
        for (int mi = 0; mi < 4; mi++) {
            int row0 = bm + warpM * 64 + mi * 16 + g;
            float2 v0, v1;
            v0.x = acc[mi][ni][0] + bx; v0.y = acc[mi][ni][1] + by;
            v1.x = acc[mi][ni][2] + bx; v1.y = acc[mi][ni][3] + by;
            if (doRelu) {
                v0.x = fmaxf(v0.x, 0.f); v0.y = fmaxf(v0.y, 0.f);
                v1.x = fmaxf(v1.x, 0.f); v1.y = fmaxf(v1.y, 0.f);
            }
            *(float2*)&C[(size_t)row0 * N + col]       = v0;
            *(float2*)&C[(size_t)(row0 + 8) * N + col] = v1;
        }
    }
}

// ======================= tf32 mma.sync flash attention =====================
// Block: 128 q-rows of one (b,h). 256 thr = 8 warps, 16 q-rows each.
// K-tiles of 64 keys. smem (dynamic): Ks[64][68], Vs[64][68], Ps[128][68].
#define ALD 68
#define ATT_SMEM ((64*ALD*2 + 128*ALD) * 4)   // 69632 bytes

__global__ void __launch_bounds__(256) attn_tc(
    const float* __restrict__ Q, const float* __restrict__ K,
    const float* __restrict__ V, float* __restrict__ O)
{
    extern __shared__ float sm[];
    float* Ks = sm;                  // [64][ALD]
    float* Vs = sm + 64 * ALD;       // [64][ALD]
    float* Ps = sm + 2 * 64 * ALD;   // [128][ALD]

    const int h = blockIdx.y;
    const int b = blockIdx.z;
    const int qbase = b * SEQ + blockIdx.x * 128;
    const int tid  = threadIdx.x;
    const int wid  = tid >> 5;
    const int lane = tid & 31;
    const int g    = lane >> 2;
    const int r    = lane & 3;
    const int m0   = wid * 16;

    // Q fragments: rows m0+g / m0+8+g, pre-scaled by 1/sqrt(64), tf32, in regs
    uint32_t qf[8][4];
    {
        const float* q0 = Q + (size_t)(qbase + m0 + g)     * DM + h * DH;
        const float* q1 = Q + (size_t)(qbase + m0 + 8 + g) * DM + h * DH;
        #pragma unroll
        for (int k8 = 0; k8 < 8; k8++) {
            qf[k8][0] = f2tf32(q0[k8*8 + r]     * 0.125f);
            qf[k8][1] = f2tf32(q1[k8*8 + r]     * 0.125f);
            qf[k8][2] = f2tf32(q0[k8*8 + 4 + r] * 0.125f);
            qf[k8][3] = f2tf32(q1[k8*8 + 4 + r] * 0.125f);
        }
    }

    float oacc[8][4];
    #pragma unroll
    for (int nt = 0; nt < 8; nt++)
        #pragma unroll
        for (int j = 0; j < 4; j++) oacc[nt][j] = 0.f;
    float m0row = -INFINITY, m1row = -INFINITY;
    float l0row = 0.f, l1row = 0.f;

    for (int kt = 0; kt < SEQ; kt += 64) {
        __syncthreads();   // previous iter's PV reads done before overwrite
        // load K/V tile (64 rows x 64 cols), tf32-convert on the way in
        #pragma unroll
        for (int rep = 0; rep < 4; rep++) {
            int idx = tid + rep * 256;
            int row = idx >> 4;
            int c4  = (idx & 15) * 4;
            const size_t base = (size_t)(b * SEQ + kt + row) * DM + h * DH + c4;
            float4 kk = *(const float4*)&K[base];
            float* kd = &Ks[row * ALD + c4];
            kd[0] = __uint_as_float(f2tf32(kk.x));
            kd[1] = __uint_as_float(f2tf32(kk.y));
            kd[2] = __uint_as_float(f2tf32(kk.z));
            kd[3] = __uint_as_float(f2tf32(kk.w));
            float4 vv = *(const float4*)&V[base];
            float* vd = &Vs[row * ALD + c4];
            vd[0] = __uint_as_float(f2tf32(vv.x));
            vd[1] = __uint_as_float(f2tf32(vv.y));
            vd[2] = __uint_as_float(f2tf32(vv.z));
            vd[3] = __uint_as_float(f2tf32(vv.w));
        }
        __syncthreads();

        // --- S = Q K^T : warp computes 16 x 64 scores ---
        float sacc[8][4];
        #pragma unroll
        for (int nt = 0; nt < 8; nt++)
            #pragma unroll
            for (int j = 0; j < 4; j++) sacc[nt][j] = 0.f;

        #pragma unroll
        for (int k8 = 0; k8 < 8; k8++) {
            uint32_t bf[8][2];
            #pragma unroll
            for (int nt = 0; nt < 8; nt++) {
                bf[nt][0] = __float_as_uint(Ks[(nt*8 + g) * ALD + k8*8 + r]);
                bf[nt][1] = __float_as_uint(Ks[(nt*8 + g) * ALD + k8*8 + 4 + r]);
            }
            #pragma unroll
            for (int nt = 0; nt < 8; nt++)
                mma16n8k8(sacc[nt], qf[k8], bf[nt]);
        }

        // --- online softmax on fragments (rows g and 8+g of warp tile) ---
        float tmax0 = -INFINITY, tmax1 = -INFINITY;
        #pragma unroll
        for (int nt = 0; nt < 8; nt++) {
            tmax0 = fmaxf(tmax0, fmaxf(sacc[nt][0], sacc[nt][1]));
            tmax1 = fmaxf(tmax1, fmaxf(sacc[nt][2], sacc[nt][3]));
        }
        tmax0 = fmaxf(tmax0, __shfl_xor_sync(0xffffffffu, tmax0, 1));
        tmax0 = fmaxf(tmax0, __shfl_xor_sync(0xffffffffu, tmax0, 2));
        tmax1 = fmaxf(tmax1, __shfl_xor_sync(0xffffffffu, tmax1, 1));
        tmax1 = fmaxf(tmax1, __shfl_xor_sync(0xffffffffu, tmax1, 2));

        const float mn0 = fmaxf(m0row, tmax0);
        const float mn1 = fmaxf(m1row, tmax1);
        const float sc0 = __expf(m0row - mn0);
        const float sc1 = __expf(m1row - mn1);
        m0row = mn0; m1row = mn1;

        float ps0 = 0.f, ps1 = 0.f;
        float* pr0 = Ps + (m0 + g)     * ALD;
        float* pr1 = Ps + (m0 + 8 + g) * ALD;
        #pragma unroll
        for (int nt = 0; nt < 8; nt++) {
            float p0 = __expf(sacc[nt][0] - mn0);
            float p1 = __expf(sacc[nt][1] - mn0);
            float p2 = __expf(sacc[nt][2] - mn1);
            float p3 = __expf(sacc[nt][3] - mn1);
            ps0 += p0 + p1; ps1 += p2 + p3;
            pr0[nt*8 + 2*r]     = __uint_as_float(f2tf32(p0));
            pr0[nt*8 + 2*r + 1] = __uint_as_float(f2tf32(p1));
            pr1[nt*8 + 2*r]     = __uint_as_float(f2tf32(p2));
            pr1[nt*8 + 2*r + 1] = __uint_as_float(f2tf32(p3));
            oacc[nt][0] *= sc0; oacc[nt][1] *= sc0;
            oacc[nt][2] *= sc1; oacc[nt][3] *= sc1;
        }
        ps0 += __shfl_xor_sync(0xffffffffu, ps0, 1);
        ps0 += __shfl_xor_sync(0xffffffffu, ps0, 2);
        ps1 += __shfl_xor_sync(0xffffffffu, ps1, 1);
        ps1 += __shfl_xor_sync(0xffffffffu, ps1, 2);
        l0row = l0row * sc0 + ps0;
        l1row = l1row * sc1 + ps1;

        __syncwarp();   // warp reads only its own 16 Ps rows — no block sync

        // --- O += P V : A = Ps (warp-local rows), B = Vs^T ---
        #pragma unroll
        for (int k8 = 0; k8 < 8; k8++) {
            uint32_t af[4];
            af[0] = __float_as_uint(Ps[(m0 + g)     * ALD + k8*8 + r]);
            af[1] = __float_as_uint(Ps[(m0 + 8 + g) * ALD + k8*8 + r]);
            af[2] = __float_as_uint(Ps[(m0 + g)     * ALD + k8*8 + 4 + r]);
            af[3] = __float_as_uint(Ps[(m0 + 8 + g) * ALD + k8*8 + 4 + r]);
            uint32_t bf[8][2];
            #pragma unroll
            for (int nt = 0; nt < 8; nt++) {
                bf[nt][0] = __float_as_uint(Vs[(k8*8 + r)     * ALD + nt*8 + g]);
                bf[nt][1] = __float_as_uint(Vs[(k8*8 + 4 + r) * ALD + nt*8 + g]);
            }
            #pragma unroll
            for (int nt = 0; nt < 8; nt++)
                mma16n8k8(oacc[nt], af, bf[nt]);
        }
    }

    // epilogue: normalize by l and store
    const float inv0 = 1.f / l0row;
    const float inv1 = 1.f / l1row;
    float* o0 = O + (size_t)(qbase + m0 + g)     * DM + h * DH;
    float* o1 = O + (size_t)(qbase + m0 + 8 + g) * DM + h * DH;
    #pragma unroll
    for (int nt = 0; nt < 8; nt++) {
        float2 v0, v1;
        v0.x = oacc[nt][0] * inv0; v0.y = oacc[nt][1] * inv0;
        v1.x = oacc[nt][2] * inv1; v1.y = oacc[nt][3] * inv1;
        *(float2*)&o0[nt*8 + 2*r] = v0;
        *(float2*)&o1[nt*8 + 2*r] = v1;
    }
}

// ---------------- residual add + LayerNorm ---------------------------------
__global__ void __launch_bounds__(256) add_ln_kernel(
    const float* __restrict__ A, const float* __restrict__ B,
    const float* __restrict__ g, const float* __restrict__ be,
    float* __restrict__ out)
{
    const int row = blockIdx.x;
    const int c   = threadIdx.x * 4;

    float4 a = *(const float4*)&A[(size_t)row * DM + c];
    float4 b = *(const float4*)&B[(size_t)row * DM + c];
    float v0 = a.x + b.x, v1 = a.y + b.y, v2 = a.z + b.z, v3 = a.w + b.w;

    float s  = v0 + v1 + v2 + v3;
    float ss = v0*v0 + v1*v1 + v2*v2 + v3*v3;

    #pragma unroll
    for (int off = 16; off > 0; off >>= 1) {
        s  += __shfl_xor_sync(0xffffffffu, s,  off);
        ss += __shfl_xor_sync(0xffffffffu, ss, off);
    }
    __shared__ float rs[8], rss[8];
    const int warp = threadIdx.x >> 5, lane = threadIdx.x & 31;
    if (lane == 0) { rs[warp] = s; rss[warp] = ss; }
    __syncthreads();
    float st = 0.f, sst = 0.f;
    #pragma unroll
    for (int w = 0; w < 8; w++) { st += rs[w]; sst += rss[w]; }

    const float mu   = st  * (1.f / DM);
    const float var  = sst * (1.f / DM) - mu * mu;
    const float rstd = rsqrtf(var + EPSLN);

    float4 gg = *(const float4*)&g[c];
    float4 bb = *(const float4*)&be[c];
    float4 o;
    o.x = (v0 - mu) * rstd * gg.x + bb.x;
    o.y = (v1 - mu) * rstd * gg.y + bb.y;
    o.z = (v2 - mu) * rstd * gg.z + bb.z;
    o.w = (v3 - mu) * rstd * gg.w + bb.w;
    *(float4*)&out[(size_t)row * DM + c] = o;
}

// ---------------- launch ----------------------------------------------------
extern "C" void kernel_launch(void* const* d_in, const int* in_sizes, int n_in,
                              void* d_out, int out_size)
{
    const float* x   = (const float*)d_in[0];
    const float* Wq  = (const float*)d_in[1];
    const float* bq  = (const float*)d_in[2];
    const float* Wk  = (const float*)d_in[3];
    const float* bk  = (const float*)d_in[4];
    const float* Wv  = (const float*)d_in[5];
    const float* bv  = (const float*)d_in[6];
    const float* Wo  = (const float*)d_in[7];
    const float* bo  = (const float*)d_in[8];
    const float* W1  = (const float*)d_in[9];
    const float* b1  = (const float*)d_in[10];
    const float* W2  = (const float*)d_in[11];
    const float* b2  = (const float*)d_in[12];
    const float* g1  = (const float*)d_in[13];
    const float* be1 = (const float*)d_in[14];
    const float* g2  = (const float*)d_in[15];
    const float* be2 = (const float*)d_in[16];
    float* out = (float*)d_out;

    float *q, *k, *v, *a, *p, *h, *f1, *f2;
    cudaGetSymbolAddress((void**)&q,  gQ);
    cudaGetSymbolAddress((void**)&k,  gK);
    cudaGetSymbolAddress((void**)&v,  gV);
    cudaGetSymbolAddress((void**)&a,  gA);
    cudaGetSymbolAddress((void**)&p,  gP);
    cudaGetSymbolAddress((void**)&h,  gH);
    cudaGetSymbolAddress((void**)&f1, gF1);
    cudaGetSymbolAddress((void**)&f2, gF2);

    static int inited = 0;
    if (!inited) {
        cudaFuncSetAttribute(attn_tc, cudaFuncAttributeMaxDynamicSharedMemorySize, ATT_SMEM);
        inited = 1;
    }

    dim3 gProj(DM / GBN,  MTOK / GBM);   // (8, 32)
    dim3 gFF1 (DFF / GBN, MTOK / GBM);   // (32, 32)

    tc_gemm<<<gProj, 256>>>(x, Wq, bq, q, MTOK, DM, DM, 0);
    tc_gemm<<<gProj, 256>>>(x, Wk, bk, k, MTOK, DM, DM, 0);
    tc_gemm<<<gProj, 256>>>(x, Wv, bv, v, MTOK, DM, DM, 0);

    attn_tc<<<dim3(SEQ / 128, NH, BATCH), 256, ATT_SMEM>>>(q, k, v, a);

    tc_gemm<<<gProj, 256>>>(a, Wo, bo, p, MTOK, DM, DM, 0);
    add_ln_kernel<<<MTOK, 256>>>(x, p, g1, be1, h);

    tc_gemm<<<gFF1, 256>>>(h, W1, b1, f1, MTOK, DFF, DM, 1);
    tc_gemm<<<gProj, 256>>>(f1, W2, b2, f2, MTOK, DM, DFF, 0);
    add_ln_kernel<<<MTOK, 256>>>(h, f2, g2, be2, out);
}

// round 8
// speedup vs baseline: 5.3786x; 1.4100x over previous
#include <cuda_runtime.h>
#include <cstdint>
#include <math.h>

#define DM    1024
#define DFF   4096
#define NH    16
#define DH    64
#define BATCH 2
#define SEQ   2048
#define MTOK  (BATCH*SEQ)   // 4096 tokens
#define EPSLN 1e-5f

// ---------------- scratch (device globals; no allocation allowed) ----------
__device__ float gQ [MTOK*DM];
__device__ float gK [MTOK*DM];
__device__ float gV [MTOK*DM];
__device__ float gA [MTOK*DM];   // attention output (concat heads)
__device__ float gP [MTOK*DM];   // attn out-proj
__device__ float gH [MTOK*DM];   // after LN1
__device__ float gF1[MTOK*DFF];  // FFN hidden
__device__ float gF2[MTOK*DM];   // FFN out

// ======================= helpers ===========================================
__device__ __forceinline__ uint32_t f2tf32(float f) {
    uint32_t r;
    asm("cvt.rna.tf32.f32 %0, %1;" : "=r"(r) : "f"(f));
    return r;
}

// warp-level tf32 MMA: D(16x8) += A(16x8) * B(8x8); valid PTX for sm_80+.
__device__ __forceinline__ void mma16n8k8(float* c, const uint32_t* a, const uint32_t* b) {
    asm volatile(
        "mma.sync.aligned.m16n8k8.row.col.f32.tf32.tf32.f32 "
        "{%0,%1,%2,%3}, {%4,%5,%6,%7}, {%8,%9}, {%0,%1,%2,%3};"
        : "+f"(c[0]), "+f"(c[1]), "+f"(c[2]), "+f"(c[3])
        : "r"(a[0]), "r"(a[1]), "r"(a[2]), "r"(a[3]), "r"(b[0]), "r"(b[1]));
}

// Permuted k-group layout: logical cols [0..7] stored at phys [0,4,1,5,2,6,3,7]
// i.e. logical r -> phys 2r, logical 4+r -> phys 2r+1. Fragment pair = LDS.64.
// Writes: phys[0..3] = {l0,l4,l1,l5}, phys[4..7] = {l2,l6,l3,l7}.

// ======================= tf32 mma.sync GEMM ================================
// C[M,N] = A[M,K] @ W[N,K]^T + bias, optional ReLU.
// Block 128x128, 256 threads = 8 warps (2 M x 4 N), warp tile 64x32.
#define GBM 128
#define GBN 128
#define GBK 32
#define LDA 40

__global__ void __launch_bounds__(256, 2) tc_gemm(
    const float* __restrict__ A, const float* __restrict__ W,
    const float* __restrict__ bias, float* __restrict__ C,
    int M, int N, int K, int doRelu)
{
    __shared__ float As[GBM * LDA];
    __shared__ float Bs[GBN * LDA];

    const int tid  = threadIdx.x;
    const int wid  = tid >> 5;
    const int lane = tid & 31;
    const int g    = lane >> 2;
    const int r    = lane & 3;
    const int warpM = wid >> 2;
    const int warpN = wid & 3;

    const int bm = blockIdx.y * GBM;
    const int bn = blockIdx.x * GBN;

    float acc[4][4][4];
    #pragma unroll
    for (int mi = 0; mi < 4; mi++)
        #pragma unroll
        for (int ni = 0; ni < 4; ni++)
            #pragma unroll
            for (int j = 0; j < 4; j++) acc[mi][ni][j] = 0.f;

    for (int k0 = 0; k0 < K; k0 += GBK) {
        __syncthreads();
        // loader: 128 rows x 4 k-groups (8 cols each), 256 thr -> 2 units each
        #pragma unroll
        for (int rep = 0; rep < 2; rep++) {
            int idx = tid + rep * 256;
            int row = idx >> 2;
            int grp = idx & 3;
            const float* pa = &A[(size_t)(bm + row) * K + k0 + grp * 8];
            float4 x0 = *(const float4*)&pa[0];
            float4 x1 = *(const float4*)&pa[4];
            float* da = &As[row * LDA + grp * 8];
            *(uint4*)&da[0] = make_uint4(f2tf32(x0.x), f2tf32(x1.x), f2tf32(x0.y), f2tf32(x1.y));
            *(uint4*)&da[4] = make_uint4(f2tf32(x0.z), f2tf32(x1.z), f2tf32(x0.w), f2tf32(x1.w));
            const float* pb = &W[(size_t)(bn + row) * K + k0 + grp * 8];
            float4 y0 = *(const float4*)&pb[0];
            float4 y1 = *(const float4*)&pb[4];
            float* db = &Bs[row * LDA + grp * 8];
            *(uint4*)&db[0] = make_uint4(f2tf32(y0.x), f2tf32(y1.x), f2tf32(y0.y), f2tf32(y1.y));
            *(uint4*)&db[4] = make_uint4(f2tf32(y0.z), f2tf32(y1.z), f2tf32(y0.w), f2tf32(y1.w));
        }
        __syncthreads();

        #pragma unroll
        for (int kt = 0; kt < GBK; kt += 8) {
            uint32_t af[4][4], bf[4][2];
            #pragma unroll
            for (int mi = 0; mi < 4; mi++) {
                int m0 = warpM * 64 + mi * 16;
                float2 t0 = *(const float2*)&As[(m0 + g)     * LDA + kt + 2*r];
                float2 t1 = *(const float2*)&As[(m0 + 8 + g) * LDA + kt + 2*r];
                af[mi][0] = __float_as_uint(t0.x);
                af[mi][1] = __float_as_uint(t1.x);
                af[mi][2] = __float_as_uint(t0.y);
                af[mi][3] = __float_as_uint(t1.y);
            }
            #pragma unroll
            for (int ni = 0; ni < 4; ni++) {
                int n0 = warpN * 32 + ni * 8;
                float2 t = *(const float2*)&Bs[(n0 + g) * LDA + kt + 2*r];
                bf[ni][0] = __float_as_uint(t.x);
                bf[ni][1] = __float_as_uint(t.y);
            }
            #pragma unroll
            for (int mi = 0; mi < 4; mi++)
                #pragma unroll
                for (int ni = 0; ni < 4; ni++)
                    mma16n8k8(acc[mi][ni], af[mi], bf[ni]);
        }
    }

    #pragma unroll
    for (int ni = 0; ni < 4; ni++) {
        int col = bn + warpN * 32 + ni * 8 + 2 * r;
        float bx = bias[col], by = bias[col + 1];
        #pragma unroll
        for (int mi = 0; mi < 4; mi++) {
            int row0 = bm + warpM * 64 + mi * 16 + g;
            float2 v0, v1;
            v0.x = acc[mi][ni][0] + bx; v0.y = acc[mi][ni][1] + by;
            v1.x = acc[mi][ni][2] + bx; v1.y = acc[mi][ni][3] + by;
            if (doRelu) {
                v0.x = fmaxf(v0.x, 0.f); v0.y = fmaxf(v0.y, 0.f);
                v1.x = fmaxf(v1.x, 0.f); v1.y = fmaxf(v1.y, 0.f);
            }
            *(float2*)&C[(size_t)row0 * N + col]       = v0;
            *(float2*)&C[(size_t)(row0 + 8) * N + col] = v1;
        }
    }
}

// ======================= tf32 mma.sync flash attention =====================
// Block: 128 q-rows of one (b,h). 128 thr = 4 warps, 32 q-rows each (2 sub-tiles).
// K-tiles of 64 keys. Dynamic smem: Ks[64][72] (dcol k-perm),
// Vt[64 dcol][72 key-perm], Ps[128][72] (key-perm).  72 ≡ 8 (mod 32) keeps the
// 8g+2r fragment addressing conflict-free, columns 0..63 now in bounds.
#define ALD 72
#define ATT_SMEM ((64*ALD + 64*ALD + 128*ALD) * 4)   // 73728 bytes

__global__ void __launch_bounds__(128) attn_tc(
    const float* __restrict__ Q, const float* __restrict__ K,
    const float* __restrict__ V, float* __restrict__ O)
{
    extern __shared__ float sm[];
    float* Ks = sm;                  // [64][ALD]
    float* Vt = sm + 64 * ALD;       // [64][ALD]
    float* Ps = sm + 128 * ALD;      // [128][ALD]

    const int h = blockIdx.y;
    const int b = blockIdx.z;
    const int qbase = b * SEQ + blockIdx.x * 128;
    const int tid  = threadIdx.x;
    const int wid  = tid >> 5;
    const int lane = tid & 31;
    const int g    = lane >> 2;
    const int r    = lane & 3;
    const int m0   = wid * 32;

    // Q fragments for 2 sub-tiles (rows m0+s*16+{g,8+g}), pre-scaled, tf32
    uint32_t qf[2][8][4];
    #pragma unroll
    for (int s = 0; s < 2; s++) {
        const float* q0 = Q + (size_t)(qbase + m0 + s*16 + g)     * DM + h * DH;
        const float* q1 = Q + (size_t)(qbase + m0 + s*16 + 8 + g) * DM + h * DH;
        #pragma unroll
        for (int k8 = 0; k8 < 8; k8++) {
            qf[s][k8][0] = f2tf32(q0[k8*8 + r]     * 0.125f);
            qf[s][k8][1] = f2tf32(q1[k8*8 + r]     * 0.125f);
            qf[s][k8][2] = f2tf32(q0[k8*8 + 4 + r] * 0.125f);
            qf[s][k8][3] = f2tf32(q1[k8*8 + 4 + r] * 0.125f);
        }
    }

    float oacc[2][8][4];
    #pragma unroll
    for (int s = 0; s < 2; s++)
        #pragma unroll
        for (int nt = 0; nt < 8; nt++)
            #pragma unroll
            for (int j = 0; j < 4; j++) oacc[s][nt][j] = 0.f;
    float mrow[2][2] = {{-INFINITY, -INFINITY}, {-INFINITY, -INFINITY}};
    float lrow[2][2] = {{0.f, 0.f}, {0.f, 0.f}};

    // phys offsets within an 8-octet for the two P cols this thread owns
    const int pc0 = 2*((2*r)   & 3) + ((2*r)   >> 2);
    const int pc1 = 2*((2*r+1) & 3) + ((2*r+1) >> 2);

    for (int kt0 = 0; kt0 < SEQ; kt0 += 64) {
        __syncthreads();
        // K loader: 64 rows x 8 col-groups, perm cols; 128 thr -> 4 units
        #pragma unroll
        for (int rep = 0; rep < 4; rep++) {
            int idx = tid + rep * 128;
            int row = idx >> 3;
            int grp = idx & 7;
            const float* src = K + (size_t)(b * SEQ + kt0 + row) * DM + h * DH + grp * 8;
            float4 x0 = *(const float4*)&src[0];
            float4 x1 = *(const float4*)&src[4];
            float* dst = &Ks[row * ALD + grp * 8];
            *(uint4*)&dst[0] = make_uint4(f2tf32(x0.x), f2tf32(x1.x), f2tf32(x0.y), f2tf32(x1.y));
            *(uint4*)&dst[4] = make_uint4(f2tf32(x0.z), f2tf32(x1.z), f2tf32(x0.w), f2tf32(x1.w));
        }
        // V loader: transpose into Vt[dcol][key-perm]; 64 keys x 16 col-segs
        #pragma unroll
        for (int rep = 0; rep < 8; rep++) {
            int idx  = tid + rep * 128;
            int key  = idx & 63;
            int cseg = idx >> 6;     // 0..15
            float4 v = *(const float4*)&V[(size_t)(b * SEQ + kt0 + key) * DM + h * DH + cseg * 4];
            int pk = (key & ~7) | (((key & 3) << 1) | ((key >> 2) & 1));
            Vt[(cseg*4 + 0) * ALD + pk] = __uint_as_float(f2tf32(v.x));
            Vt[(cseg*4 + 1) * ALD + pk] = __uint_as_float(f2tf32(v.y));
            Vt[(cseg*4 + 2) * ALD + pk] = __uint_as_float(f2tf32(v.z));
            Vt[(cseg*4 + 3) * ALD + pk] = __uint_as_float(f2tf32(v.w));
        }
        __syncthreads();

        // --- per sub-tile: S = Q K^T, online softmax, P -> smem ---
        #pragma unroll
        for (int s = 0; s < 2; s++) {
            float sacc[8][4];
            #pragma unroll
            for (int nt = 0; nt < 8; nt++)
                #pragma unroll
                for (int j = 0; j < 4; j++) sacc[nt][j] = 0.f;

            #pragma unroll
            for (int k8 = 0; k8 < 8; k8++) {
                uint32_t bf[8][2];
                #pragma unroll
                for (int nt = 0; nt < 8; nt++) {
                    float2 t = *(const float2*)&Ks[(nt*8 + g) * ALD + k8*8 + 2*r];
                    bf[nt][0] = __float_as_uint(t.x);
                    bf[nt][1] = __float_as_uint(t.y);
                }
                #pragma unroll
                for (int nt = 0; nt < 8; nt++)
                    mma16n8k8(sacc[nt], qf[s][k8], bf[nt]);
            }

            float tmax0 = -INFINITY, tmax1 = -INFINITY;
            #pragma unroll
            for (int nt = 0; nt < 8; nt++) {
                tmax0 = fmaxf(tmax0, fmaxf(sacc[nt][0], sacc[nt][1]));
                tmax1 = fmaxf(tmax1, fmaxf(sacc[nt][2], sacc[nt][3]));
            }
            tmax0 = fmaxf(tmax0, __shfl_xor_sync(0xffffffffu, tmax0, 1));
            tmax0 = fmaxf(tmax0, __shfl_xor_sync(0xffffffffu, tmax0, 2));
            tmax1 = fmaxf(tmax1, __shfl_xor_sync(0xffffffffu, tmax1, 1));
            tmax1 = fmaxf(tmax1, __shfl_xor_sync(0xffffffffu, tmax1, 2));

            const float mn0 = fmaxf(mrow[s][0], tmax0);
            const float mn1 = fmaxf(mrow[s][1], tmax1);
            const float sc0 = __expf(mrow[s][0] - mn0);
            const float sc1 = __expf(mrow[s][1] - mn1);
            mrow[s][0] = mn0; mrow[s][1] = mn1;

            float ps0 = 0.f, ps1 = 0.f;
            float* pr0 = Ps + (m0 + s*16 + g)     * ALD;
            float* pr1 = Ps + (m0 + s*16 + 8 + g) * ALD;
            #pragma unroll
            for (int nt = 0; nt < 8; nt++) {
                float p0 = __expf(sacc[nt][0] - mn0);
                float p1 = __expf(sacc[nt][1] - mn0);
                float p2 = __expf(sacc[nt][2] - mn1);
                float p3 = __expf(sacc[nt][3] - mn1);
                ps0 += p0 + p1; ps1 += p2 + p3;
                pr0[nt*8 + pc0] = __uint_as_float(f2tf32(p0));
                pr0[nt*8 + pc1] = __uint_as_float(f2tf32(p1));
                pr1[nt*8 + pc0] = __uint_as_float(f2tf32(p2));
                pr1[nt*8 + pc1] = __uint_as_float(f2tf32(p3));
                oacc[s][nt][0] *= sc0; oacc[s][nt][1] *= sc0;
                oacc[s][nt][2] *= sc1; oacc[s][nt][3] *= sc1;
            }
            ps0 += __shfl_xor_sync(0xffffffffu, ps0, 1);
            ps0 += __shfl_xor_sync(0xffffffffu, ps0, 2);
            ps1 += __shfl_xor_sync(0xffffffffu, ps1, 1);
            ps1 += __shfl_xor_sync(0xffffffffu, ps1, 2);
            lrow[s][0] = lrow[s][0] * sc0 + ps0;
            lrow[s][1] = lrow[s][1] * sc1 + ps1;
        }

        __syncwarp();   // warp reads only its own 32 Ps rows

        // --- O += P V : V B-frags shared across both sub-tiles ---
        #pragma unroll
        for (int k8 = 0; k8 < 8; k8++) {
            uint32_t vb[8][2];
            #pragma unroll
            for (int nt = 0; nt < 8; nt++) {
                float2 t = *(const float2*)&Vt[(nt*8 + g) * ALD + k8*8 + 2*r];
                vb[nt][0] = __float_as_uint(t.x);
                vb[nt][1] = __float_as_uint(t.y);
            }
            #pragma unroll
            for (int s = 0; s < 2; s++) {
                float2 pa = *(const float2*)&Ps[(m0 + s*16 + g)     * ALD + k8*8 + 2*r];
                float2 pb = *(const float2*)&Ps[(m0 + s*16 + 8 + g) * ALD + k8*8 + 2*r];
                uint32_t af[4];
                af[0] = __float_as_uint(pa.x);
                af[1] = __float_as_uint(pb.x);
                af[2] = __float_as_uint(pa.y);
                af[3] = __float_as_uint(pb.y);
                #pragma unroll
                for (int nt = 0; nt < 8; nt++)
                    mma16n8k8(oacc[s][nt], af, vb[nt]);
            }
        }
    }

    // epilogue: normalize and store
    #pragma unroll
    for (int s = 0; s < 2; s++) {
        const float inv0 = 1.f / lrow[s][0];
        const float inv1 = 1.f / lrow[s][1];
        float* o0 = O + (size_t)(qbase + m0 + s*16 + g)     * DM + h * DH;
        float* o1 = O + (size_t)(qbase + m0 + s*16 + 8 + g) * DM + h * DH;
        #pragma unroll
        for (int nt = 0; nt < 8; nt++) {
            float2 v0, v1;
            v0.x = oacc[s][nt][0] * inv0; v0.y = oacc[s][nt][1] * inv0;
            v1.x = oacc[s][nt][2] * inv1; v1.y = oacc[s][nt][3] * inv1;
            *(float2*)&o0[nt*8 + 2*r] = v0;
            *(float2*)&o1[nt*8 + 2*r] = v1;
        }
    }
}

// ---------------- residual add + LayerNorm ---------------------------------
__global__ void __launch_bounds__(256) add_ln_kernel(
    const float* __restrict__ A, const float* __restrict__ B,
    const float* __restrict__ g, const float* __restrict__ be,
    float* __restrict__ out)
{
    const int row = blockIdx.x;
    const int c   = threadIdx.x * 4;

    float4 a = *(const float4*)&A[(size_t)row * DM + c];
    float4 b = *(const float4*)&B[(size_t)row * DM + c];
    float v0 = a.x + b.x, v1 = a.y + b.y, v2 = a.z + b.z, v3 = a.w + b.w;

    float s  = v0 + v1 + v2 + v3;
    float ss = v0*v0 + v1*v1 + v2*v2 + v3*v3;

    #pragma unroll
    for (int off = 16; off > 0; off >>= 1) {
        s  += __shfl_xor_sync(0xffffffffu, s,  off);
        ss += __shfl_xor_sync(0xffffffffu, ss, off);
    }
    __shared__ float rs[8], rss[8];
    const int warp = threadIdx.x >> 5, lane = threadIdx.x & 31;
    if (lane == 0) { rs[warp] = s; rss[warp] = ss; }
    __syncthreads();
    float st = 0.f, sst = 0.f;
    #pragma unroll
    for (int w = 0; w < 8; w++) { st += rs[w]; sst += rss[w]; }

    const float mu   = st  * (1.f / DM);
    const float var  = sst * (1.f / DM) - mu * mu;
    const float rstd = rsqrtf(var + EPSLN);

    float4 gg = *(const float4*)&g[c];
    float4 bb = *(const float4*)&be[c];
    float4 o;
    o.x = (v0 - mu) * rstd * gg.x + bb.x;
    o.y = (v1 - mu) * rstd * gg.y + bb.y;
    o.z = (v2 - mu) * rstd * gg.z + bb.z;
    o.w = (v3 - mu) * rstd * gg.w + bb.w;
    *(float4*)&out[(size_t)row * DM + c] = o;
}

// ---------------- launch ----------------------------------------------------
extern "C" void kernel_launch(void* const* d_in, const int* in_sizes, int n_in,
                              void* d_out, int out_size)
{
    const float* x   = (const float*)d_in[0];
    const float* Wq  = (const float*)d_in[1];
    const float* bq  = (const float*)d_in[2];
    const float* Wk  = (const float*)d_in[3];
    const float* bk  = (const float*)d_in[4];
    const float* Wv  = (const float*)d_in[5];
    const float* bv  = (const float*)d_in[6];
    const float* Wo  = (const float*)d_in[7];
    const float* bo  = (const float*)d_in[8];
    const float* W1  = (const float*)d_in[9];
    const float* b1  = (const float*)d_in[10];
    const float* W2  = (const float*)d_in[11];
    const float* b2  = (const float*)d_in[12];
    const float* g1  = (const float*)d_in[13];
    const float* be1 = (const float*)d_in[14];
    const float* g2  = (const float*)d_in[15];
    const float* be2 = (const float*)d_in[16];
    float* out = (float*)d_out;

    float *q, *k, *v, *a, *p, *h, *f1, *f2;
    cudaGetSymbolAddress((void**)&q,  gQ);
    cudaGetSymbolAddress((void**)&k,  gK);
    cudaGetSymbolAddress((void**)&v,  gV);
    cudaGetSymbolAddress((void**)&a,  gA);
    cudaGetSymbolAddress((void**)&p,  gP);
    cudaGetSymbolAddress((void**)&h,  gH);
    cudaGetSymbolAddress((void**)&f1, gF1);
    cudaGetSymbolAddress((void**)&f2, gF2);

    cudaFuncSetAttribute(attn_tc, cudaFuncAttributeMaxDynamicSharedMemorySize, ATT_SMEM);

    dim3 gProj(DM / GBN,  MTOK / GBM);   // (8, 32)
    dim3 gFF1 (DFF / GBN, MTOK / GBM);   // (32, 32)

    tc_gemm<<<gProj, 256>>>(x, Wq, bq, q, MTOK, DM, DM, 0);
    tc_gemm<<<gProj, 256>>>(x, Wk, bk, k, MTOK, DM, DM, 0);
    tc_gemm<<<gProj, 256>>>(x, Wv, bv, v, MTOK, DM, DM, 0);

    attn_tc<<<dim3(SEQ / 128, NH, BATCH), 128, ATT_SMEM>>>(q, k, v, a);

    tc_gemm<<<gProj, 256>>>(a, Wo, bo, p, MTOK, DM, DM, 0);
    add_ln_kernel<<<MTOK, 256>>>(x, p, g1, be1, h);

    tc_gemm<<<gFF1, 256>>>(h, W1, b1, f1, MTOK, DFF, DM, 1);
    tc_gemm<<<gProj, 256>>>(f1, W2, b2, f2, MTOK, DM, DFF, 0);
    add_ln_kernel<<<MTOK, 256>>>(h, f2, g2, be2, out);
}

// round 9
// speedup vs baseline: 6.6574x; 1.2378x over previous
#include <cuda_runtime.h>
#include <cuda_fp16.h>
#include <cstdint>
#include <math.h>

#define DM    1024
#define DFF   4096
#define NH    16
#define DH    64
#define BATCH 2
#define SEQ   2048
#define MTOK  (BATCH*SEQ)   // 4096 tokens
#define EPSLN 1e-5f

// ---------------- scratch (device globals; no allocation allowed) ----------
__device__ float gQ [MTOK*DM];
__device__ float gK [MTOK*DM];
__device__ float gV [MTOK*DM];
__device__ float gA [MTOK*DM];   // attention output (concat heads)
__device__ float gP [MTOK*DM];   // attn out-proj
__device__ float gH [MTOK*DM];   // after LN1
__device__ float gF1[MTOK*DFF];  // FFN hidden
__device__ float gF2[MTOK*DM];   // FFN out

// ======================= helpers ===========================================
__device__ __forceinline__ uint32_t h2(float a, float b) {
    __half2 v = __floats2half2_rn(a, b);
    return *(uint32_t*)&v;
}

// warp-level fp16 MMA: D(16x8,f32) += A(16x16,f16) * B(16x8,f16)
__device__ __forceinline__ void mma16n8k16(float* c, const uint32_t* a, const uint32_t* b) {
    asm volatile(
        "mma.sync.aligned.m16n8k16.row.col.f32.f16.f16.f32 "
        "{%0,%1,%2,%3}, {%4,%5,%6,%7}, {%8,%9}, {%0,%1,%2,%3};"
        : "+f"(c[0]), "+f"(c[1]), "+f"(c[2]), "+f"(c[3])
        : "r"(a[0]), "r"(a[1]), "r"(a[2]), "r"(a[3]), "r"(b[0]), "r"(b[1]));
}

// smem stored as uint32 half2-words. Each 8-word group covers 16 k-columns.
// Permuted order [w0,w4,w1,w5,w2,w6,w3,w7]: fragment word pair (r, 4+r)
// lands at phys (2r, 2r+1) -> one LDS.64.

// ======================= fp16 mma.sync GEMM ================================
// C[M,N] = A[M,K] @ W[N,K]^T + bias, optional ReLU.
// Block 128x128, 256 threads = 8 warps (2 M x 4 N), warp tile 64x32, BK=64.
#define GBM 128
#define GBN 128
#define GBK 64
#define LDW 40     // word pitch (40 ≡ 8 mod 32: conflict-free fragment LDS.64)

__global__ void __launch_bounds__(256, 2) tc_gemm(
    const float* __restrict__ A, const float* __restrict__ W,
    const float* __restrict__ bias, float* __restrict__ C,
    int M, int N, int K, int doRelu)
{
    __shared__ uint32_t As[GBM * LDW];
    __shared__ uint32_t Bs[GBN * LDW];

    const int tid  = threadIdx.x;
    const int wid  = tid >> 5;
    const int lane = tid & 31;
    const int g    = lane >> 2;
    const int r    = lane & 3;
    const int warpM = wid >> 2;
    const int warpN = wid & 3;

    const int bm = blockIdx.y * GBM;
    const int bn = blockIdx.x * GBN;

    float acc[4][4][4];
    #pragma unroll
    for (int mi = 0; mi < 4; mi++)
        #pragma unroll
        for (int ni = 0; ni < 4; ni++)
            #pragma unroll
            for (int j = 0; j < 4; j++) acc[mi][ni][j] = 0.f;

    for (int k0 = 0; k0 < K; k0 += GBK) {
        __syncthreads();
        // loader: 128 rows x 4 groups (16 cols each); 256 thr -> 2 units each
        #pragma unroll
        for (int rep = 0; rep < 2; rep++) {
            int idx = tid + rep * 256;
            int row = idx >> 2;
            int grp = idx & 3;
            const float* pa = &A[(size_t)(bm + row) * K + k0 + grp * 16];
            float4 x0 = *(const float4*)&pa[0];
            float4 x1 = *(const float4*)&pa[4];
            float4 x2 = *(const float4*)&pa[8];
            float4 x3 = *(const float4*)&pa[12];
            uint32_t* da = &As[row * LDW + grp * 8];
            *(uint4*)&da[0] = make_uint4(h2(x0.x,x0.y), h2(x2.x,x2.y), h2(x0.z,x0.w), h2(x2.z,x2.w));
            *(uint4*)&da[4] = make_uint4(h2(x1.x,x1.y), h2(x3.x,x3.y), h2(x1.z,x1.w), h2(x3.z,x3.w));
            const float* pb = &W[(size_t)(bn + row) * K + k0 + grp * 16];
            float4 y0 = *(const float4*)&pb[0];
            float4 y1 = *(const float4*)&pb[4];
            float4 y2 = *(const float4*)&pb[8];
            float4 y3 = *(const float4*)&pb[12];
            uint32_t* db = &Bs[row * LDW + grp * 8];
            *(uint4*)&db[0] = make_uint4(h2(y0.x,y0.y), h2(y2.x,y2.y), h2(y0.z,y0.w), h2(y2.z,y2.w));
            *(uint4*)&db[4] = make_uint4(h2(y1.x,y1.y), h2(y3.x,y3.y), h2(y1.z,y1.w), h2(y3.z,y3.w));
        }
        __syncthreads();

        #pragma unroll
        for (int c = 0; c < 4; c++) {    // 4 chunks of k=16
            uint32_t af[4][4], bf[4][2];
            #pragma unroll
            for (int mi = 0; mi < 4; mi++) {
                int m0r = warpM * 64 + mi * 16;
                uint2 t0 = *(const uint2*)&As[(m0r + g)     * LDW + c*8 + 2*r];
                uint2 t1 = *(const uint2*)&As[(m0r + 8 + g) * LDW + c*8 + 2*r];
                af[mi][0] = t0.x; af[mi][1] = t1.x;
                af[mi][2] = t0.y; af[mi][3] = t1.y;
            }
            #pragma unroll
            for (int ni = 0; ni < 4; ni++) {
                int n0 = warpN * 32 + ni * 8;
                uint2 t = *(const uint2*)&Bs[(n0 + g) * LDW + c*8 + 2*r];
                bf[ni][0] = t.x; bf[ni][1] = t.y;
            }
            #pragma unroll
            for (int mi = 0; mi < 4; mi++)
                #pragma unroll
                for (int ni = 0; ni < 4; ni++)
                    mma16n8k16(acc[mi][ni], af[mi], bf[ni]);
        }
    }

    #pragma unroll
    for (int ni = 0; ni < 4; ni++) {
        int col = bn + warpN * 32 + ni * 8 + 2 * r;
        float bx = bias[col], by = bias[col + 1];
        #pragma unroll
        for (int mi = 0; mi < 4; mi++) {
            int row0 = bm + warpM * 64 + mi * 16 + g;
            float2 v0, v1;
            v0.x = acc[mi][ni][0] + bx; v0.y = acc[mi][ni][1] + by;
            v1.x = acc[mi][ni][2] + bx; v1.y = acc[mi][ni][3] + by;
            if (doRelu) {
                v0.x = fmaxf(v0.x, 0.f); v0.y = fmaxf(v0.y, 0.f);
                v1.x = fmaxf(v1.x, 0.f); v1.y = fmaxf(v1.y, 0.f);
            }
            *(float2*)&C[(size_t)row0 * N + col]       = v0;
            *(float2*)&C[(size_t)(row0 + 8) * N + col] = v1;
        }
    }
}

// ======================= fp16 mma.sync flash attention =====================
// Block: 128 q-rows of one (b,h). 128 thr = 4 warps, 32 q-rows each (2 sub-tiles).
// K-tiles of 64 keys. smem words: Ks[64][40] (dcol words, k-perm),
// Vt[64 dcol][40] (key words, perm), Ps[128][40] (key words, perm).
#define ALD 40

__global__ void __launch_bounds__(128) attn_tc(
    const float* __restrict__ Q, const float* __restrict__ K,
    const float* __restrict__ V, float* __restrict__ O)
{
    __shared__ uint32_t Ks[64 * ALD];
    __shared__ uint32_t Vt[64 * ALD];
    __shared__ uint32_t Ps[128 * ALD];

    const int h = blockIdx.y;
    const int b = blockIdx.z;
    const int qbase = b * SEQ + blockIdx.x * 128;
    const int tid  = threadIdx.x;
    const int wid  = tid >> 5;
    const int lane = tid & 31;
    const int g    = lane >> 2;
    const int r    = lane & 3;
    const int m0   = wid * 32;

    // Q fragments (half2), pre-scaled by 1/sqrt(64): 4 chunks of k=16 per sub-tile
    uint32_t qf[2][4][4];
    #pragma unroll
    for (int s = 0; s < 2; s++) {
        const float* q0 = Q + (size_t)(qbase + m0 + s*16 + g)     * DM + h * DH;
        const float* q1 = Q + (size_t)(qbase + m0 + s*16 + 8 + g) * DM + h * DH;
        #pragma unroll
        for (int c = 0; c < 4; c++) {
            qf[s][c][0] = h2(q0[c*16 + 2*r]     * 0.125f, q0[c*16 + 2*r + 1]     * 0.125f);
            qf[s][c][1] = h2(q1[c*16 + 2*r]     * 0.125f, q1[c*16 + 2*r + 1]     * 0.125f);
            qf[s][c][2] = h2(q0[c*16 + 8 + 2*r] * 0.125f, q0[c*16 + 8 + 2*r + 1] * 0.125f);
            qf[s][c][3] = h2(q1[c*16 + 8 + 2*r] * 0.125f, q1[c*16 + 8 + 2*r + 1] * 0.125f);
        }
    }

    float oacc[2][8][4];
    #pragma unroll
    for (int s = 0; s < 2; s++)
        #pragma unroll
        for (int nt = 0; nt < 8; nt++)
            #pragma unroll
            for (int j = 0; j < 4; j++) oacc[s][nt][j] = 0.f;
    float mrow[2][2] = {{-INFINITY, -INFINITY}, {-INFINITY, -INFINITY}};
    float lrow[2][2] = {{0.f, 0.f}, {0.f, 0.f}};

    for (int kt0 = 0; kt0 < SEQ; kt0 += 64) {
        __syncthreads();
        // K loader: 64 keys x 4 groups (16 dcols); 128 thr -> 2 units
        #pragma unroll
        for (int rep = 0; rep < 2; rep++) {
            int idx = tid + rep * 128;
            int key = idx >> 2;
            int grp = idx & 3;
            const float* src = K + (size_t)(b * SEQ + kt0 + key) * DM + h * DH + grp * 16;
            float4 x0 = *(const float4*)&src[0];
            float4 x1 = *(const float4*)&src[4];
            float4 x2 = *(const float4*)&src[8];
            float4 x3 = *(const float4*)&src[12];
            uint32_t* dst = &Ks[key * ALD + grp * 8];
            *(uint4*)&dst[0] = make_uint4(h2(x0.x,x0.y), h2(x2.x,x2.y), h2(x0.z,x0.w), h2(x2.z,x2.w));
            *(uint4*)&dst[4] = make_uint4(h2(x1.x,x1.y), h2(x3.x,x3.y), h2(x1.z,x1.w), h2(x3.z,x3.w));
        }
        // V loader: transpose -> Vt[dcol][key word], perm within 8-word groups.
        // unit = key pair x 4 dcols; 32*16 = 512 units; 128 thr -> 4 units
        #pragma unroll
        for (int rep = 0; rep < 4; rep++) {
            int idx = tid + rep * 128;
            int kp  = idx & 31;    // key pair (keys 2kp, 2kp+1)
            int dq  = idx >> 5;    // dcol quad 0..15
            const size_t base = (size_t)(b * SEQ + kt0 + 2*kp) * DM + h * DH + dq * 4;
            float4 va = *(const float4*)&V[base];
            float4 vb = *(const float4*)&V[base + DM];
            int lcl = kp & 7;
            int pw  = (kp >> 3) * 8 + ((lcl < 4) ? 2*lcl : 2*lcl - 7);
            Vt[(dq*4 + 0) * ALD + pw] = h2(va.x, vb.x);
            Vt[(dq*4 + 1) * ALD + pw] = h2(va.y, vb.y);
            Vt[(dq*4 + 2) * ALD + pw] = h2(va.z, vb.z);
            Vt[(dq*4 + 3) * ALD + pw] = h2(va.w, vb.w);
        }
        __syncthreads();

        // --- per sub-tile: S = Q K^T, online softmax, P -> smem ---
        #pragma unroll
        for (int s = 0; s < 2; s++) {
            float sacc[8][4];
            #pragma unroll
            for (int nt = 0; nt < 8; nt++)
                #pragma unroll
                for (int j = 0; j < 4; j++) sacc[nt][j] = 0.f;

            #pragma unroll
            for (int c = 0; c < 4; c++) {
                uint32_t bf[8][2];
                #pragma unroll
                for (int nt = 0; nt < 8; nt++) {
                    uint2 t = *(const uint2*)&Ks[(nt*8 + g) * ALD + c*8 + 2*r];
                    bf[nt][0] = t.x; bf[nt][1] = t.y;
                }
                #pragma unroll
                for (int nt = 0; nt < 8; nt++)
                    mma16n8k16(sacc[nt], qf[s][c], bf[nt]);
            }

            float tmax0 = -INFINITY, tmax1 = -INFINITY;
            #pragma unroll
            for (int nt = 0; nt < 8; nt++) {
                tmax0 = fmaxf(tmax0, fmaxf(sacc[nt][0], sacc[nt][1]));
                tmax1 = fmaxf(tmax1, fmaxf(sacc[nt][2], sacc[nt][3]));
            }
            tmax0 = fmaxf(tmax0, __shfl_xor_sync(0xffffffffu, tmax0, 1));
            tmax0 = fmaxf(tmax0, __shfl_xor_sync(0xffffffffu, tmax0, 2));
            tmax1 = fmaxf(tmax1, __shfl_xor_sync(0xffffffffu, tmax1, 1));
            tmax1 = fmaxf(tmax1, __shfl_xor_sync(0xffffffffu, tmax1, 2));

            const float mn0 = fmaxf(mrow[s][0], tmax0);
            const float mn1 = fmaxf(mrow[s][1], tmax1);
            const float sc0 = __expf(mrow[s][0] - mn0);
            const float sc1 = __expf(mrow[s][1] - mn1);
            mrow[s][0] = mn0; mrow[s][1] = mn1;

            float ps0 = 0.f, ps1 = 0.f;
            uint32_t* pr0 = Ps + (m0 + s*16 + g)     * ALD;
            uint32_t* pr1 = Ps + (m0 + s*16 + 8 + g) * ALD;
            #pragma unroll
            for (int nt = 0; nt < 8; nt++) {
                float p0 = __expf(sacc[nt][0] - mn0);
                float p1 = __expf(sacc[nt][1] - mn0);
                float p2 = __expf(sacc[nt][2] - mn1);
                float p3 = __expf(sacc[nt][3] - mn1);
                ps0 += p0 + p1; ps1 += p2 + p3;
                int pw = (nt >> 1) * 8 + 2*r + (nt & 1);
                pr0[pw] = h2(p0, p1);
                pr1[pw] = h2(p2, p3);
                oacc[s][nt][0] *= sc0; oacc[s][nt][1] *= sc0;
                oacc[s][nt][2] *= sc1; oacc[s][nt][3] *= sc1;
            }
            ps0 += __shfl_xor_sync(0xffffffffu, ps0, 1);
            ps0 += __shfl_xor_sync(0xffffffffu, ps0, 2);
            ps1 += __shfl_xor_sync(0xffffffffu, ps1, 1);
            ps1 += __shfl_xor_sync(0xffffffffu, ps1, 2);
            lrow[s][0] = lrow[s][0] * sc0 + ps0;
            lrow[s][1] = lrow[s][1] * sc1 + ps1;
        }

        __syncwarp();   // warp reads only its own 32 Ps rows

        // --- O += P V : V B-frags shared across both sub-tiles ---
        #pragma unroll
        for (int c = 0; c < 4; c++) {
            uint32_t vb[8][2];
            #pragma unroll
            for (int nt = 0; nt < 8; nt++) {
                uint2 t = *(const uint2*)&Vt[(nt*8 + g) * ALD + c*8 + 2*r];
                vb[nt][0] = t.x; vb[nt][1] = t.y;
            }
            #pragma unroll
            for (int s = 0; s < 2; s++) {
                uint2 pa = *(const uint2*)&Ps[(m0 + s*16 + g)     * ALD + c*8 + 2*r];
                uint2 pb = *(const uint2*)&Ps[(m0 + s*16 + 8 + g) * ALD + c*8 + 2*r];
                uint32_t af[4];
                af[0] = pa.x; af[1] = pb.x; af[2] = pa.y; af[3] = pb.y;
                #pragma unroll
                for (int nt = 0; nt < 8; nt++)
                    mma16n8k16(oacc[s][nt], af, vb[nt]);
            }
        }
    }

    // epilogue: normalize and store
    #pragma unroll
    for (int s = 0; s < 2; s++) {
        const float inv0 = 1.f / lrow[s][0];
        const float inv1 = 1.f / lrow[s][1];
        float* o0 = O + (size_t)(qbase + m0 + s*16 + g)     * DM + h * DH;
        float* o1 = O + (size_t)(qbase + m0 + s*16 + 8 + g) * DM + h * DH;
        #pragma unroll
        for (int nt = 0; nt < 8; nt++) {
            float2 v0, v1;
            v0.x = oacc[s][nt][0] * inv0; v0.y = oacc[s][nt][1] * inv0;
            v1.x = oacc[s][nt][2] * inv1; v1.y = oacc[s][nt][3] * inv1;
            *(float2*)&o0[nt*8 + 2*r] = v0;
            *(float2*)&o1[nt*8 + 2*r] = v1;
        }
    }
}

// ---------------- residual add + LayerNorm ---------------------------------
__global__ void __launch_bounds__(256) add_ln_kernel(
    const float* __restrict__ A, const float* __restrict__ B,
    const float* __restrict__ g, const float* __restrict__ be,
    float* __restrict__ out)
{
    const int row = blockIdx.x;
    const int c   = threadIdx.x * 4;

    float4 a = *(const float4*)&A[(size_t)row * DM + c];
    float4 b = *(const float4*)&B[(size_t)row * DM + c];
    float v0 = a.x + b.x, v1 = a.y + b.y, v2 = a.z + b.z, v3 = a.w + b.w;

    float s  = v0 + v1 + v2 + v3;
    float ss = v0*v0 + v1*v1 + v2*v2 + v3*v3;

    #pragma unroll
    for (int off = 16; off > 0; off >>= 1) {
        s  += __shfl_xor_sync(0xffffffffu, s,  off);
        ss += __shfl_xor_sync(0xffffffffu, ss, off);
    }
    __shared__ float rs[8], rss[8];
    const int warp = threadIdx.x >> 5, lane = threadIdx.x & 31;
    if (lane == 0) { rs[warp] = s; rss[warp] = ss; }
    __syncthreads();
    float st = 0.f, sst = 0.f;
    #pragma unroll
    for (int w = 0; w < 8; w++) { st += rs[w]; sst += rss[w]; }

    const float mu   = st  * (1.f / DM);
    const float var  = sst * (1.f / DM) - mu * mu;
    const float rstd = rsqrtf(var + EPSLN);

    float4 gg = *(const float4*)&g[c];
    float4 bb = *(const float4*)&be[c];
    float4 o;
    o.x = (v0 - mu) * rstd * gg.x + bb.x;
    o.y = (v1 - mu) * rstd * gg.y + bb.y;
    o.z = (v2 - mu) * rstd * gg.z + bb.z;
    o.w = (v3 - mu) * rstd * gg.w + bb.w;
    *(float4*)&out[(size_t)row * DM + c] = o;
}

// ---------------- launch ----------------------------------------------------
extern "C" void kernel_launch(void* const* d_in, const int* in_sizes, int n_in,
                              void* d_out, int out_size)
{
    const float* x   = (const float*)d_in[0];
    const float* Wq  = (const float*)d_in[1];
    const float* bq  = (const float*)d_in[2];
    const float* Wk  = (const float*)d_in[3];
    const float* bk  = (const float*)d_in[4];
    const float* Wv  = (const float*)d_in[5];
    const float* bv  = (const float*)d_in[6];
    const float* Wo  = (const float*)d_in[7];
    const float* bo  = (const float*)d_in[8];
    const float* W1  = (const float*)d_in[9];
    const float* b1  = (const float*)d_in[10];
    const float* W2  = (const float*)d_in[11];
    const float* b2  = (const float*)d_in[12];
    const float* g1  = (const float*)d_in[13];
    const float* be1 = (const float*)d_in[14];
    const float* g2  = (const float*)d_in[15];
    const float* be2 = (const float*)d_in[16];
    float* out = (float*)d_out;

    float *q, *k, *v, *a, *p, *h, *f1, *f2;
    cudaGetSymbolAddress((void**)&q,  gQ);
    cudaGetSymbolAddress((void**)&k,  gK);
    cudaGetSymbolAddress((void**)&v,  gV);
    cudaGetSymbolAddress((void**)&a,  gA);
    cudaGetSymbolAddress((void**)&p,  gP);
    cudaGetSymbolAddress((void**)&h,  gH);
    cudaGetSymbolAddress((void**)&f1, gF1);
    cudaGetSymbolAddress((void**)&f2, gF2);

    dim3 gProj(DM / GBN,  MTOK / GBM);   // (8, 32)
    dim3 gFF1 (DFF / GBN, MTOK / GBM);   // (32, 32)

    tc_gemm<<<gProj, 256>>>(x, Wq, bq, q, MTOK, DM, DM, 0);
    tc_gemm<<<gProj, 256>>>(x, Wk, bk, k, MTOK, DM, DM, 0);
    tc_gemm<<<gProj, 256>>>(x, Wv, bv, v, MTOK, DM, DM, 0);

    attn_tc<<<dim3(SEQ / 128, NH, BATCH), 128>>>(q, k, v, a);

    tc_gemm<<<gProj, 256>>>(a, Wo, bo, p, MTOK, DM, DM, 0);
    add_ln_kernel<<<MTOK, 256>>>(x, p, g1, be1, h);

    tc_gemm<<<gFF1, 256>>>(h, W1, b1, f1, MTOK, DFF, DM, 1);
    tc_gemm<<<gProj, 256>>>(f1, W2, b2, f2, MTOK, DM, DFF, 0);
    add_ln_kernel<<<MTOK, 256>>>(h, f2, g2, be2, out);
}

// round 10
// speedup vs baseline: 11.0396x; 1.6583x over previous
#include <cuda_runtime.h>
#include <cuda_fp16.h>
#include <cstdint>
#include <math.h>

#define DM    1024
#define DFF   4096
#define NH    16
#define DH    64
#define BATCH 2
#define SEQ   2048
#define MTOK  (BATCH*SEQ)   // 4096 tokens
#define EPSLN 1e-5f

// ---------------- scratch (device globals; no allocation allowed) ----------
__device__ float  gP [MTOK*DM];   // attn out-proj (fp32)
__device__ float  gH [MTOK*DM];   // after LN1 (fp32, residual for LN2)
__device__ float  gF2[MTOK*DM];   // FFN out (fp32)
__device__ __half hX [MTOK*DM];
__device__ __half hQ [MTOK*DM];
__device__ __half hK [MTOK*DM];
__device__ __half hV [MTOK*DM];
__device__ __half hA [MTOK*DM];
__device__ __half hH [MTOK*DM];
__device__ __half hF1[MTOK*DFF];
__device__ __half hWq[DM*DM];
__device__ __half hWk[DM*DM];
__device__ __half hWv[DM*DM];
__device__ __half hWo[DM*DM];
__device__ __half hW1[DFF*DM];
__device__ __half hW2[DM*DFF];

// ======================= helpers ===========================================
__device__ __forceinline__ uint32_t scast(const void* p) {
    return (uint32_t)__cvta_generic_to_shared(p);
}
__device__ __forceinline__ void cp16(uint32_t dst, const void* src) {
    asm volatile("cp.async.cg.shared.global [%0], [%1], 16;" :: "r"(dst), "l"(src));
}
__device__ __forceinline__ void cp_commit() {
    asm volatile("cp.async.commit_group;" ::: "memory");
}
__device__ __forceinline__ void ldsm4(uint32_t* d, uint32_t a) {
    asm volatile("ldmatrix.sync.aligned.m8n8.x4.shared.b16 {%0,%1,%2,%3}, [%4];"
                 : "=r"(d[0]), "=r"(d[1]), "=r"(d[2]), "=r"(d[3]) : "r"(a));
}
__device__ __forceinline__ void ldsm4t(uint32_t* d, uint32_t a) {
    asm volatile("ldmatrix.sync.aligned.m8n8.x4.trans.shared.b16 {%0,%1,%2,%3}, [%4];"
                 : "=r"(d[0]), "=r"(d[1]), "=r"(d[2]), "=r"(d[3]) : "r"(a));
}
__device__ __forceinline__ uint32_t h2(float a, float b) {
    __half2 v = __floats2half2_rn(a, b);
    return *(uint32_t*)&v;
}
__device__ __forceinline__ void mma16n8k16(float* c, const uint32_t* a, const uint32_t* b) {
    asm volatile(
        "mma.sync.aligned.m16n8k16.row.col.f32.f16.f16.f32 "
        "{%0,%1,%2,%3}, {%4,%5,%6,%7}, {%8,%9}, {%0,%1,%2,%3};"
        : "+f"(c[0]), "+f"(c[1]), "+f"(c[2]), "+f"(c[3])
        : "r"(a[0]), "r"(a[1]), "r"(a[2]), "r"(a[3]), "r"(b[0]), "r"(b[1]));
}

// tile rows are 64 halves = 128B = 8 chunks of 16B; chunk swizzle: c ^ (row&7)
#define SWOFF(row, c) ((row) * 128 + (((c) ^ ((row) & 7)) << 4))

// ---------------- fp32 -> fp16 prepass -------------------------------------
__global__ void __launch_bounds__(256) f2h_kernel(const float* __restrict__ in,
                                                 __half* __restrict__ out) {
    int i = (blockIdx.x * 256 + threadIdx.x) * 4;
    float4 v = *(const float4*)&in[i];
    *(uint2*)&out[i] = make_uint2(h2(v.x, v.y), h2(v.z, v.w));
}

// ======================= fp16 cp.async + ldmatrix GEMM =====================
// C = A[M,K] @ W[N,K]^T + bias; optional ReLU, scale; fp32 and/or fp16 out.
// Block 128x128, 256 thr = 8 warps (2M x 4N), warp tile 64x32, BK=64, 2 stages.
#define GBM 128
#define GBN 128
#define GBK 64
#define GSTAGE (128*128)        // 16KB per matrix per stage
#define GSMEM  (4*GSTAGE)       // 64KB

__global__ void __launch_bounds__(256, 2) tc_gemm(
    const __half* __restrict__ A, const __half* __restrict__ W,
    const float* __restrict__ bias, float* __restrict__ Cf, __half* __restrict__ Ch,
    int M, int N, int K, int doRelu, float scale)
{
    extern __shared__ char smem[];
    const int tid  = threadIdx.x;
    const int wid  = tid >> 5;
    const int lane = tid & 31;
    const int g    = lane >> 2;
    const int r    = lane & 3;
    const int warpM = wid >> 2;
    const int warpN = wid & 3;
    const int bm = blockIdx.y * GBM;
    const int bn = blockIdx.x * GBN;

    // loader: 2 threads per row, 4 chunks each
    const int lrow = tid >> 1;
    const int lc0  = (tid & 1) * 4;
    const __half* agp = &A[(size_t)(bm + lrow) * K + lc0 * 8];
    const __half* wgp = &W[(size_t)(bn + lrow) * K + lc0 * 8];

    // fragment lane addressing
    const int arow = lane & 15;                       // A/row offset within 16
    const int acx  = lane >> 4;                       // A chunk low bit
    const int brow = (lane & 7) + ((lane >> 4) << 3); // B row offset within 16
    const int bcx  = (lane >> 3) & 1;                 // B chunk low bit

    float acc[4][4][4];
    #pragma unroll
    for (int mi = 0; mi < 4; mi++)
        #pragma unroll
        for (int ni = 0; ni < 4; ni++)
            #pragma unroll
            for (int j = 0; j < 4; j++) acc[mi][ni][j] = 0.f;

    const int nIter = K / GBK;

    // prologue: stage 0
    {
        uint32_t da = scast(smem) + lrow * 128;
        uint32_t db = scast(smem + 2*GSTAGE) + lrow * 128;
        #pragma unroll
        for (int c = 0; c < 4; c++) {
            int ch = lc0 + c;
            cp16(da + (((ch ^ (lrow & 7)) << 4)), agp + c * 8);
            cp16(db + (((ch ^ (lrow & 7)) << 4)), wgp + c * 8);
        }
        cp_commit();
    }

    for (int it = 0; it < nIter; it++) {
        if (it + 1 < nIter) {
            int s = (it + 1) & 1;
            int k0 = (it + 1) * GBK;
            uint32_t da = scast(smem + s*GSTAGE) + lrow * 128;
            uint32_t db = scast(smem + (2+s)*GSTAGE) + lrow * 128;
            #pragma unroll
            for (int c = 0; c < 4; c++) {
                int ch = lc0 + c;
                cp16(da + ((ch ^ (lrow & 7)) << 4), agp + k0 + c * 8);
                cp16(db + ((ch ^ (lrow & 7)) << 4), wgp + k0 + c * 8);
            }
            cp_commit();
            asm volatile("cp.async.wait_group 1;" ::: "memory");
        } else {
            asm volatile("cp.async.wait_group 0;" ::: "memory");
        }
        __syncthreads();

        const uint32_t abase = scast(smem + (it & 1) * GSTAGE);
        const uint32_t bbase = scast(smem + (2 + (it & 1)) * GSTAGE);

        #pragma unroll
        for (int c2 = 0; c2 < 4; c2++) {
            uint32_t af[4][4], bf[4][2];
            #pragma unroll
            for (int mi = 0; mi < 4; mi++) {
                int row = warpM * 64 + mi * 16 + arow;
                int ch  = 2 * c2 + acx;
                ldsm4(af[mi], abase + SWOFF(row, ch));
            }
            #pragma unroll
            for (int p = 0; p < 2; p++) {
                int row = warpN * 32 + p * 16 + brow;
                int ch  = 2 * c2 + bcx;
                uint32_t t[4];
                ldsm4(t, bbase + SWOFF(row, ch));
                bf[2*p][0]   = t[0]; bf[2*p][1]   = t[1];
                bf[2*p+1][0] = t[2]; bf[2*p+1][1] = t[3];
            }
            #pragma unroll
            for (int mi = 0; mi < 4; mi++)
                #pragma unroll
                for (int ni = 0; ni < 4; ni++)
                    mma16n8k16(acc[mi][ni], af[mi], bf[ni]);
        }
        __syncthreads();
    }

    // epilogue
    #pragma unroll
    for (int ni = 0; ni < 4; ni++) {
        int col = bn + warpN * 32 + ni * 8 + 2 * r;
        float bx = bias[col], by = bias[col + 1];
        #pragma unroll
        for (int mi = 0; mi < 4; mi++) {
            int row0 = bm + warpM * 64 + mi * 16 + g;
            float2 v0, v1;
            v0.x = (acc[mi][ni][0] + bx) * scale; v0.y = (acc[mi][ni][1] + by) * scale;
            v1.x = (acc[mi][ni][2] + bx) * scale; v1.y = (acc[mi][ni][3] + by) * scale;
            if (doRelu) {
                v0.x = fmaxf(v0.x, 0.f); v0.y = fmaxf(v0.y, 0.f);
                v1.x = fmaxf(v1.x, 0.f); v1.y = fmaxf(v1.y, 0.f);
            }
            if (Cf) {
                *(float2*)&Cf[(size_t)row0 * N + col]       = v0;
                *(float2*)&Cf[(size_t)(row0 + 8) * N + col] = v1;
            }
            if (Ch) {
                *(uint32_t*)&Ch[(size_t)row0 * N + col]       = h2(v0.x, v0.y);
                *(uint32_t*)&Ch[(size_t)(row0 + 8) * N + col] = h2(v1.x, v1.y);
            }
        }
    }
}

// ======================= fp16 flash attention ==============================
// Block: 128 q-rows of one (b,h). 128 thr = 4 warps, 32 q-rows (2 sub-tiles).
// K/V tiles [64][64] fp16, cp.async + XOR swizzle, frags via ldmatrix.
// Ps: R8's proven permuted half2-word layout, pitch 40 words.
#define ALD 40

__global__ void __launch_bounds__(128) attn_tc(
    const __half* __restrict__ Q, const __half* __restrict__ K,
    const __half* __restrict__ V, __half* __restrict__ O)
{
    __shared__ char  KsB[64 * 128];
    __shared__ char  VsB[64 * 128];
    __shared__ uint32_t Ps[128 * ALD];

    const int h = blockIdx.y;
    const int b = blockIdx.z;
    const int qbase = b * SEQ + blockIdx.x * 128;
    const int tid  = threadIdx.x;
    const int wid  = tid >> 5;
    const int lane = tid & 31;
    const int g    = lane >> 2;
    const int r    = lane & 3;
    const int m0   = wid * 32;

    const uint32_t ksb = scast(KsB);
    const uint32_t vsb = scast(VsB);

    // Q fragments (already scaled by 1/8 in the Q GEMM epilogue)
    uint32_t qf[2][4][4];
    #pragma unroll
    for (int s = 0; s < 2; s++) {
        const __half* q0 = Q + (size_t)(qbase + m0 + s*16 + g)     * DM + h * DH;
        const __half* q1 = Q + (size_t)(qbase + m0 + s*16 + 8 + g) * DM + h * DH;
        #pragma unroll
        for (int c = 0; c < 4; c++) {
            qf[s][c][0] = *(const uint32_t*)&q0[c*16 + 2*r];
            qf[s][c][1] = *(const uint32_t*)&q1[c*16 + 2*r];
            qf[s][c][2] = *(const uint32_t*)&q0[c*16 + 8 + 2*r];
            qf[s][c][3] = *(const uint32_t*)&q1[c*16 + 8 + 2*r];
        }
    }

    float oacc[2][8][4];
    #pragma unroll
    for (int s = 0; s < 2; s++)
        #pragma unroll
        for (int nt = 0; nt < 8; nt++)
            #pragma unroll
            for (int j = 0; j < 4; j++) oacc[s][nt][j] = 0.f;
    float mrow[2][2] = {{-INFINITY, -INFINITY}, {-INFINITY, -INFINITY}};
    float lrow[2][2] = {{0.f, 0.f}, {0.f, 0.f}};

    // fragment lane addressing (same derivation as GEMM)
    const int brow = (lane & 7) + ((lane >> 4) << 3);   // K (QK^T B-frags)
    const int bcx  = (lane >> 3) & 1;
    const int vrow = (lane & 7) + (((lane >> 3) & 1) << 3);  // V (.trans B-frags)
    const int vcx  = lane >> 4;

    for (int kt0 = 0; kt0 < SEQ; kt0 += 64) {
        __syncthreads();   // previous iteration's frag reads done
        // cp.async K and V tiles: 512 chunks each, 128 thr -> 4 each
        #pragma unroll
        for (int i = 0; i < 4; i++) {
            int idx = tid + i * 128;
            int row = idx >> 3;
            int c   = idx & 7;
            const size_t src = (size_t)(b * SEQ + kt0 + row) * DM + h * DH + c * 8;
            cp16(ksb + SWOFF(row, c), K + src);
            cp16(vsb + SWOFF(row, c), V + src);
        }
        cp_commit();
        asm volatile("cp.async.wait_group 0;" ::: "memory");
        __syncthreads();

        // --- per sub-tile: S = Q K^T, online softmax, P -> smem ---
        #pragma unroll
        for (int s = 0; s < 2; s++) {
            float sacc[8][4];
            #pragma unroll
            for (int nt = 0; nt < 8; nt++)
                #pragma unroll
                for (int j = 0; j < 4; j++) sacc[nt][j] = 0.f;

            #pragma unroll
            for (int c2 = 0; c2 < 4; c2++) {
                uint32_t bf[8][2];
                #pragma unroll
                for (int np = 0; np < 4; np++) {
                    int row = np * 16 + brow;
                    int ch  = 2 * c2 + bcx;
                    uint32_t t[4];
                    ldsm4(t, ksb + SWOFF(row, ch));
                    bf[2*np][0]   = t[0]; bf[2*np][1]   = t[1];
                    bf[2*np+1][0] = t[2]; bf[2*np+1][1] = t[3];
                }
                #pragma unroll
                for (int nt = 0; nt < 8; nt++)
                    mma16n8k16(sacc[nt], qf[s][c2], bf[nt]);
            }

            float tmax0 = -INFINITY, tmax1 = -INFINITY;
            #pragma unroll
            for (int nt = 0; nt < 8; nt++) {
                tmax0 = fmaxf(tmax0, fmaxf(sacc[nt][0], sacc[nt][1]));
                tmax1 = fmaxf(tmax1, fmaxf(sacc[nt][2], sacc[nt][3]));
            }
            tmax0 = fmaxf(tmax0, __shfl_xor_sync(0xffffffffu, tmax0, 1));
            tmax0 = fmaxf(tmax0, __shfl_xor_sync(0xffffffffu, tmax0, 2));
            tmax1 = fmaxf(tmax1, __shfl_xor_sync(0xffffffffu, tmax1, 1));
            tmax1 = fmaxf(tmax1, __shfl_xor_sync(0xffffffffu, tmax1, 2));

            const float mn0 = fmaxf(mrow[s][0], tmax0);
            const float mn1 = fmaxf(mrow[s][1], tmax1);
            const float sc0 = __expf(mrow[s][0] - mn0);
            const float sc1 = __expf(mrow[s][1] - mn1);
            mrow[s][0] = mn0; mrow[s][1] = mn1;

            float ps0 = 0.f, ps1 = 0.f;
            uint32_t* pr0 = Ps + (m0 + s*16 + g)     * ALD;
            uint32_t* pr1 = Ps + (m0 + s*16 + 8 + g) * ALD;
            #pragma unroll
            for (int nt = 0; nt < 8; nt++) {
                float p0 = __expf(sacc[nt][0] - mn0);
                float p1 = __expf(sacc[nt][1] - mn0);
                float p2 = __expf(sacc[nt][2] - mn1);
                float p3 = __expf(sacc[nt][3] - mn1);
                ps0 += p0 + p1; ps1 += p2 + p3;
                int pw = (nt >> 1) * 8 + 2*r + (nt & 1);
                pr0[pw] = h2(p0, p1);
                pr1[pw] = h2(p2, p3);
                oacc[s][nt][0] *= sc0; oacc[s][nt][1] *= sc0;
                oacc[s][nt][2] *= sc1; oacc[s][nt][3] *= sc1;
            }
            ps0 += __shfl_xor_sync(0xffffffffu, ps0, 1);
            ps0 += __shfl_xor_sync(0xffffffffu, ps0, 2);
            ps1 += __shfl_xor_sync(0xffffffffu, ps1, 1);
            ps1 += __shfl_xor_sync(0xffffffffu, ps1, 2);
            lrow[s][0] = lrow[s][0] * sc0 + ps0;
            lrow[s][1] = lrow[s][1] * sc1 + ps1;
        }

        __syncwarp();   // warp reads only its own 32 Ps rows

        // --- O += P V : V B-frags via ldmatrix.trans, shared across sub-tiles
        #pragma unroll
        for (int c2 = 0; c2 < 4; c2++) {
            uint32_t vb[8][2];
            #pragma unroll
            for (int np = 0; np < 4; np++) {
                int row = 16 * c2 + vrow;      // stored row = key
                int ch  = 2 * np + vcx;        // chunk = dcol group
                uint32_t t[4];
                ldsm4t(t, vsb + SWOFF(row, ch));
                vb[2*np][0]   = t[0]; vb[2*np][1]   = t[1];
                vb[2*np+1][0] = t[2]; vb[2*np+1][1] = t[3];
            }
            #pragma unroll
            for (int s = 0; s < 2; s++) {
                uint2 pa = *(const uint2*)&Ps[(m0 + s*16 + g)     * ALD + c2*8 + 2*r];
                uint2 pb = *(const uint2*)&Ps[(m0 + s*16 + 8 + g) * ALD + c2*8 + 2*r];
                uint32_t af[4];
                af[0] = pa.x; af[1] = pb.x; af[2] = pa.y; af[3] = pb.y;
                #pragma unroll
                for (int nt = 0; nt < 8; nt++)
                    mma16n8k16(oacc[s][nt], af, vb[nt]);
            }
        }
    }

    // epilogue: normalize, fp16 store
    #pragma unroll
    for (int s = 0; s < 2; s++) {
        const float inv0 = 1.f / lrow[s][0];
        const float inv1 = 1.f / lrow[s][1];
        __half* o0 = O + (size_t)(qbase + m0 + s*16 + g)     * DM + h * DH;
        __half* o1 = O + (size_t)(qbase + m0 + s*16 + 8 + g) * DM + h * DH;
        #pragma unroll
        for (int nt = 0; nt < 8; nt++) {
            *(uint32_t*)&o0[nt*8 + 2*r] = h2(oacc[s][nt][0] * inv0, oacc[s][nt][1] * inv0);
            *(uint32_t*)&o1[nt*8 + 2*r] = h2(oacc[s][nt][2] * inv1, oacc[s][nt][3] * inv1);
        }
    }
}

// ---------------- residual add + LayerNorm (optional fp16 copy) ------------
__global__ void __launch_bounds__(256) add_ln_kernel(
    const float* __restrict__ A, const float* __restrict__ B,
    const float* __restrict__ g, const float* __restrict__ be,
    float* __restrict__ out, __half* __restrict__ outh)
{
    const int row = blockIdx.x;
    const int c   = threadIdx.x * 4;

    float4 a = *(const float4*)&A[(size_t)row * DM + c];
    float4 b = *(const float4*)&B[(size_t)row * DM + c];
    float v0 = a.x + b.x, v1 = a.y + b.y, v2 = a.z + b.z, v3 = a.w + b.w;

    float s  = v0 + v1 + v2 + v3;
    float ss = v0*v0 + v1*v1 + v2*v2 + v3*v3;

    #pragma unroll
    for (int off = 16; off > 0; off >>= 1) {
        s  += __shfl_xor_sync(0xffffffffu, s,  off);
        ss += __shfl_xor_sync(0xffffffffu, ss, off);
    }
    __shared__ float rs[8], rss[8];
    const int warp = threadIdx.x >> 5, lane = threadIdx.x & 31;
    if (lane == 0) { rs[warp] = s; rss[warp] = ss; }
    __syncthreads();
    float st = 0.f, sst = 0.f;
    #pragma unroll
    for (int w = 0; w < 8; w++) { st += rs[w]; sst += rss[w]; }

    const float mu   = st  * (1.f / DM);
    const float var  = sst * (1.f / DM) - mu * mu;
    const float rstd = rsqrtf(var + EPSLN);

    float4 gg = *(const float4*)&g[c];
    float4 bb = *(const float4*)&be[c];
    float4 o;
    o.x = (v0 - mu) * rstd * gg.x + bb.x;
    o.y = (v1 - mu) * rstd * gg.y + bb.y;
    o.z = (v2 - mu) * rstd * gg.z + bb.z;
    o.w = (v3 - mu) * rstd * gg.w + bb.w;
    *(float4*)&out[(size_t)row * DM + c] = o;
    if (outh)
        *(uint2*)&outh[(size_t)row * DM + c] = make_uint2(h2(o.x, o.y), h2(o.z, o.w));
}

// ---------------- launch ----------------------------------------------------
extern "C" void kernel_launch(void* const* d_in, const int* in_sizes, int n_in,
                              void* d_out, int out_size)
{
    const float* x   = (const float*)d_in[0];
    const float* Wq  = (const float*)d_in[1];
    const float* bq  = (const float*)d_in[2];
    const float* Wk  = (const float*)d_in[3];
    const float* bk  = (const float*)d_in[4];
    const float* Wv  = (const float*)d_in[5];
    const float* bv  = (const float*)d_in[6];
    const float* Wo  = (const float*)d_in[7];
    const float* bo  = (const float*)d_in[8];
    const float* W1  = (const float*)d_in[9];
    const float* b1  = (const float*)d_in[10];
    const float* W2  = (const float*)d_in[11];
    const float* b2  = (const float*)d_in[12];
    const float* g1  = (const float*)d_in[13];
    const float* be1 = (const float*)d_in[14];
    const float* g2  = (const float*)d_in[15];
    const float* be2 = (const float*)d_in[16];
    float* out = (float*)d_out;

    float *p, *hbuf, *f2;
    __half *xh, *qh, *kh, *vh, *ah, *hh, *f1h;
    __half *wqh, *wkh, *wvh, *woh, *w1h, *w2h;
    cudaGetSymbolAddress((void**)&p,    gP);
    cudaGetSymbolAddress((void**)&hbuf, gH);
    cudaGetSymbolAddress((void**)&f2,   gF2);
    cudaGetSymbolAddress((void**)&xh,  hX);
    cudaGetSymbolAddress((void**)&qh,  hQ);
    cudaGetSymbolAddress((void**)&kh,  hK);
    cudaGetSymbolAddress((void**)&vh,  hV);
    cudaGetSymbolAddress((void**)&ah,  hA);
    cudaGetSymbolAddress((void**)&hh,  hH);
    cudaGetSymbolAddress((void**)&f1h, hF1);
    cudaGetSymbolAddress((void**)&wqh, hWq);
    cudaGetSymbolAddress((void**)&wkh, hWk);
    cudaGetSymbolAddress((void**)&wvh, hWv);
    cudaGetSymbolAddress((void**)&woh, hWo);
    cudaGetSymbolAddress((void**)&w1h, hW1);
    cudaGetSymbolAddress((void**)&w2h, hW2);

    cudaFuncSetAttribute(tc_gemm, cudaFuncAttributeMaxDynamicSharedMemorySize, GSMEM);

    // prepass: fp32 -> fp16 (x + weights)
    f2h_kernel<<<MTOK*DM/1024, 256>>>(x,  xh);
    f2h_kernel<<<DM*DM/1024,  256>>>(Wq, wqh);
    f2h_kernel<<<DM*DM/1024,  256>>>(Wk, wkh);
    f2h_kernel<<<DM*DM/1024,  256>>>(Wv, wvh);
    f2h_kernel<<<DM*DM/1024,  256>>>(Wo, woh);
    f2h_kernel<<<DFF*DM/1024, 256>>>(W1, w1h);
    f2h_kernel<<<DM*DFF/1024, 256>>>(W2, w2h);

    dim3 gProj(DM / GBN,  MTOK / GBM);   // (8, 32)
    dim3 gFF1 (DFF / GBN, MTOK / GBM);   // (32, 32)

    // q scaled by 1/sqrt(64) in epilogue
    tc_gemm<<<gProj, 256, GSMEM>>>(xh, wqh, bq, nullptr, qh, MTOK, DM, DM, 0, 0.125f);
    tc_gemm<<<gProj, 256, GSMEM>>>(xh, wkh, bk, nullptr, kh, MTOK, DM, DM, 0, 1.f);
    tc_gemm<<<gProj, 256, GSMEM>>>(xh, wvh, bv, nullptr, vh, MTOK, DM, DM, 0, 1.f);

    attn_tc<<<dim3(SEQ / 128, NH, BATCH), 128>>>(qh, kh, vh, ah);

    tc_gemm<<<gProj, 256, GSMEM>>>(ah, woh, bo, p, nullptr, MTOK, DM, DM, 0, 1.f);
    add_ln_kernel<<<MTOK, 256>>>(x, p, g1, be1, hbuf, hh);

    tc_gemm<<<gFF1, 256, GSMEM>>>(hh, w1h, b1, nullptr, f1h, MTOK, DFF, DM, 1, 1.f);
    tc_gemm<<<gProj, 256, GSMEM>>>(f1h, w2h, b2, f2, nullptr, MTOK, DM, DFF, 0, 1.f);
    add_ln_kernel<<<MTOK, 256>>>(hbuf, f2, g2, be2, out, nullptr);
}

// round 11
// speedup vs baseline: 11.2559x; 1.0196x over previous
#include <cuda_runtime.h>
#include <cuda_fp16.h>
#include <cstdint>
#include <math.h>

#define DM    1024
#define DFF   4096
#define NH    16
#define DH    64
#define BATCH 2
#define SEQ   2048
#define MTOK  (BATCH*SEQ)   // 4096 tokens
#define QKVS  3072          // packed qkv row stride
#define EPSLN 1e-5f

// ---------------- scratch (device globals; no allocation allowed) ----------
__device__ float  gP [MTOK*DM];     // attn out-proj (fp32)
__device__ float  gH [MTOK*DM];     // after LN1 (fp32, residual for LN2)
__device__ float  gF2[MTOK*DM];     // FFN out (fp32)
__device__ float  gBqkv[QKVS];      // packed bias (bq*0.125, bk, bv)
__device__ __half hX  [MTOK*DM];
__device__ __half hQKV[MTOK*QKVS];  // packed q|k|v
__device__ __half hA  [MTOK*DM];
__device__ __half hH  [MTOK*DM];
__device__ __half hF1 [MTOK*DFF];
__device__ __half hWqkv[QKVS*DM];   // packed Wq*0.125|Wk|Wv
__device__ __half hWo[DM*DM];
__device__ __half hW1[DFF*DM];
__device__ __half hW2[DM*DFF];

// ======================= helpers ===========================================
__device__ __forceinline__ uint32_t scast(const void* p) {
    return (uint32_t)__cvta_generic_to_shared(p);
}
__device__ __forceinline__ void cp16(uint32_t dst, const void* src) {
    asm volatile("cp.async.cg.shared.global [%0], [%1], 16;" :: "r"(dst), "l"(src));
}
__device__ __forceinline__ void cp_commit() {
    asm volatile("cp.async.commit_group;" ::: "memory");
}
__device__ __forceinline__ void ldsm4(uint32_t* d, uint32_t a) {
    asm volatile("ldmatrix.sync.aligned.m8n8.x4.shared.b16 {%0,%1,%2,%3}, [%4];"
                 : "=r"(d[0]), "=r"(d[1]), "=r"(d[2]), "=r"(d[3]) : "r"(a));
}
__device__ __forceinline__ void ldsm4t(uint32_t* d, uint32_t a) {
    asm volatile("ldmatrix.sync.aligned.m8n8.x4.trans.shared.b16 {%0,%1,%2,%3}, [%4];"
                 : "=r"(d[0]), "=r"(d[1]), "=r"(d[2]), "=r"(d[3]) : "r"(a));
}
__device__ __forceinline__ uint32_t h2(float a, float b) {
    __half2 v = __floats2half2_rn(a, b);
    return *(uint32_t*)&v;
}
__device__ __forceinline__ void mma16n8k16(float* c, const uint32_t* a, const uint32_t* b) {
    asm volatile(
        "mma.sync.aligned.m16n8k16.row.col.f32.f16.f16.f32 "
        "{%0,%1,%2,%3}, {%4,%5,%6,%7}, {%8,%9}, {%0,%1,%2,%3};"
        : "+f"(c[0]), "+f"(c[1]), "+f"(c[2]), "+f"(c[3])
        : "r"(a[0]), "r"(a[1]), "r"(a[2]), "r"(a[3]), "r"(b[0]), "r"(b[1]));
}

// tile rows are 64 halves = 128B = 8 chunks of 16B; chunk swizzle: c ^ (row&7)
#define SWOFF(row, c) ((row) * 128 + (((c) ^ ((row) & 7)) << 4))

// ---------------- prepass kernels ------------------------------------------
__global__ void __launch_bounds__(256) f2h_kernel(const float* __restrict__ in,
                                                 __half* __restrict__ out) {
    int i = (blockIdx.x * 256 + threadIdx.x) * 8;
    float4 v0 = *(const float4*)&in[i];
    float4 v1 = *(const float4*)&in[i + 4];
    *(uint4*)&out[i] = make_uint4(h2(v0.x, v0.y), h2(v0.z, v0.w),
                                  h2(v1.x, v1.y), h2(v1.z, v1.w));
}
// pack Wq*0.125 | Wk | Wv  -> hWqkv
__global__ void __launch_bounds__(256) packw_kernel(
    const float* __restrict__ Wq, const float* __restrict__ Wk,
    const float* __restrict__ Wv, __half* __restrict__ out) {
    int i = (blockIdx.x * 256 + threadIdx.x) * 4;
    float4 q = *(const float4*)&Wq[i];
    float4 k = *(const float4*)&Wk[i];
    float4 v = *(const float4*)&Wv[i];
    *(uint2*)&out[i]           = make_uint2(h2(q.x*0.125f, q.y*0.125f), h2(q.z*0.125f, q.w*0.125f));
    *(uint2*)&out[DM*DM + i]   = make_uint2(h2(k.x, k.y), h2(k.z, k.w));
    *(uint2*)&out[2*DM*DM + i] = make_uint2(h2(v.x, v.y), h2(v.z, v.w));
}
__global__ void __launch_bounds__(1024) packb_kernel(
    const float* __restrict__ bq, const float* __restrict__ bk,
    const float* __restrict__ bv, float* __restrict__ out) {
    int i = blockIdx.x * 1024 + threadIdx.x;
    float v = (blockIdx.x == 0) ? bq[i] * 0.125f
            : (blockIdx.x == 1) ? bk[i - DM] : bv[i - 2*DM];
    out[i] = v;
}

// ======================= fp16 3-stage cp.async GEMM ========================
// C = A[M,K] @ W[N,K]^T + bias; optional ReLU; fp32 and/or fp16 out.
// Block 128x128, 256 thr = 8 warps (2M x 4N), warp tile 64x32, BK=64, 3 stages.
#define GBM 128
#define GBN 128
#define GBK 64
#define GSTAGE (128*128)          // 16KB per matrix per stage
#define GSMEM  (6*GSTAGE)         // 96KB

__global__ void __launch_bounds__(256, 2) tc_gemm(
    const __half* __restrict__ A, const __half* __restrict__ W,
    const float* __restrict__ bias, float* __restrict__ Cf, __half* __restrict__ Ch,
    int M, int N, int K, int doRelu)
{
    extern __shared__ char smem[];
    const int tid  = threadIdx.x;
    const int wid  = tid >> 5;
    const int lane = tid & 31;
    const int g    = lane >> 2;
    const int r    = lane & 3;
    const int warpM = wid >> 2;
    const int warpN = wid & 3;
    const int bm = blockIdx.y * GBM;
    const int bn = blockIdx.x * GBN;

    const int lrow = tid >> 1;
    const int lc0  = (tid & 1) * 4;
    const __half* agp = &A[(size_t)(bm + lrow) * K + lc0 * 8];
    const __half* wgp = &W[(size_t)(bn + lrow) * K + lc0 * 8];

    const int arow = lane & 15;
    const int acx  = lane >> 4;
    const int brow = (lane & 7) + ((lane >> 4) << 3);
    const int bcx  = (lane >> 3) & 1;

    float acc[4][4][4];
    #pragma unroll
    for (int mi = 0; mi < 4; mi++)
        #pragma unroll
        for (int ni = 0; ni < 4; ni++)
            #pragma unroll
            for (int j = 0; j < 4; j++) acc[mi][ni][j] = 0.f;

    const int nIter = K / GBK;

    // stage loader (one commit group per stage: A + B chunks)
    auto load_stage = [&](int it) {
        int s  = it - (it / 3) * 3;
        int k0 = it * GBK;
        uint32_t da = scast(smem + s * GSTAGE) + lrow * 128;
        uint32_t db = scast(smem + (3 + s) * GSTAGE) + lrow * 128;
        #pragma unroll
        for (int c = 0; c < 4; c++) {
            int ch = lc0 + c;
            cp16(da + ((ch ^ (lrow & 7)) << 4), agp + k0 + c * 8);
            cp16(db + ((ch ^ (lrow & 7)) << 4), wgp + k0 + c * 8);
        }
        cp_commit();
    };

    load_stage(0);
    load_stage(1);

    for (int it = 0; it < nIter; it++) {
        if (it < nIter - 1) asm volatile("cp.async.wait_group 1;" ::: "memory");
        else                asm volatile("cp.async.wait_group 0;" ::: "memory");
        __syncthreads();
        if (it + 2 < nIter) load_stage(it + 2);   // target buf (it-1)%3: idle

        int s = it - (it / 3) * 3;
        const uint32_t abase = scast(smem + s * GSTAGE);
        const uint32_t bbase = scast(smem + (3 + s) * GSTAGE);

        #pragma unroll
        for (int c2 = 0; c2 < 4; c2++) {
            uint32_t af[4][4], bf[4][2];
            #pragma unroll
            for (int mi = 0; mi < 4; mi++) {
                int row = warpM * 64 + mi * 16 + arow;
                ldsm4(af[mi], abase + SWOFF(row, 2 * c2 + acx));
            }
            #pragma unroll
            for (int p = 0; p < 2; p++) {
                int row = warpN * 32 + p * 16 + brow;
                uint32_t t[4];
                ldsm4(t, bbase + SWOFF(row, 2 * c2 + bcx));
                bf[2*p][0]   = t[0]; bf[2*p][1]   = t[1];
                bf[2*p+1][0] = t[2]; bf[2*p+1][1] = t[3];
            }
            #pragma unroll
            for (int mi = 0; mi < 4; mi++)
                #pragma unroll
                for (int ni = 0; ni < 4; ni++)
                    mma16n8k16(acc[mi][ni], af[mi], bf[ni]);
        }
        __syncthreads();   // all frag reads done before stage reuse next iter
    }

    #pragma unroll
    for (int ni = 0; ni < 4; ni++) {
        int col = bn + warpN * 32 + ni * 8 + 2 * r;
        float bx = bias[col], by = bias[col + 1];
        #pragma unroll
        for (int mi = 0; mi < 4; mi++) {
            int row0 = bm + warpM * 64 + mi * 16 + g;
            float2 v0, v1;
            v0.x = acc[mi][ni][0] + bx; v0.y = acc[mi][ni][1] + by;
            v1.x = acc[mi][ni][2] + bx; v1.y = acc[mi][ni][3] + by;
            if (doRelu) {
                v0.x = fmaxf(v0.x, 0.f); v0.y = fmaxf(v0.y, 0.f);
                v1.x = fmaxf(v1.x, 0.f); v1.y = fmaxf(v1.y, 0.f);
            }
            if (Cf) {
                *(float2*)&Cf[(size_t)row0 * N + col]       = v0;
                *(float2*)&Cf[(size_t)(row0 + 8) * N + col] = v1;
            }
            if (Ch) {
                *(uint32_t*)&Ch[(size_t)row0 * N + col]       = h2(v0.x, v0.y);
                *(uint32_t*)&Ch[(size_t)(row0 + 8) * N + col] = h2(v1.x, v1.y);
            }
        }
    }
}

// ======================= fp16 flash attention (double-buffered) ============
// Block: 128 q-rows of one (b,h). 128 thr = 4 warps, 32 q-rows (2 sub-tiles).
// Dynamic smem: Ks[2][8KB], Vs[2][8KB], Ps[20KB] = 53248 B.
#define ALD 40
#define ATILE 8192
#define ATT_SMEM (4*ATILE + 128*ALD*4)

__global__ void __launch_bounds__(128) attn_tc(
    const __half* __restrict__ QKV, __half* __restrict__ O)
{
    extern __shared__ char smem[];
    const uint32_t base = scast(smem);
    uint32_t* Ps = (uint32_t*)(smem + 4*ATILE);

    const int h = blockIdx.y;
    const int b = blockIdx.z;
    const int qbase = b * SEQ + blockIdx.x * 128;
    const int tid  = threadIdx.x;
    const int wid  = tid >> 5;
    const int lane = tid & 31;
    const int g    = lane >> 2;
    const int r    = lane & 3;
    const int m0   = wid * 32;

    // tile loader: K+V for tile t into buffer s (one commit group)
    auto load_tile = [&](int t, int s) {
        uint32_t kd = base + s * ATILE;
        uint32_t vd = base + 2 * ATILE + s * ATILE;
        #pragma unroll
        for (int i = 0; i < 4; i++) {
            int idx = tid + i * 128;
            int row = idx >> 3;
            int c   = idx & 7;
            const size_t rb = (size_t)(b * SEQ + t * 64 + row) * QKVS + h * DH + c * 8;
            cp16(kd + SWOFF(row, c), QKV + rb + DM);      // K section
            cp16(vd + SWOFF(row, c), QKV + rb + 2 * DM);  // V section
        }
        cp_commit();
    };

    // Q fragments (1/sqrt(64) folded into Wq/bq)
    uint32_t qf[2][4][4];
    #pragma unroll
    for (int s = 0; s < 2; s++) {
        const __half* q0 = QKV + (size_t)(qbase + m0 + s*16 + g)     * QKVS + h * DH;
        const __half* q1 = QKV + (size_t)(qbase + m0 + s*16 + 8 + g) * QKVS + h * DH;
        #pragma unroll
        for (int c = 0; c < 4; c++) {
            qf[s][c][0] = *(const uint32_t*)&q0[c*16 + 2*r];
            qf[s][c][1] = *(const uint32_t*)&q1[c*16 + 2*r];
            qf[s][c][2] = *(const uint32_t*)&q0[c*16 + 8 + 2*r];
            qf[s][c][3] = *(const uint32_t*)&q1[c*16 + 8 + 2*r];
        }
    }

    float oacc[2][8][4];
    #pragma unroll
    for (int s = 0; s < 2; s++)
        #pragma unroll
        for (int nt = 0; nt < 8; nt++)
            #pragma unroll
            for (int j = 0; j < 4; j++) oacc[s][nt][j] = 0.f;
    float mrow[2][2] = {{-INFINITY, -INFINITY}, {-INFINITY, -INFINITY}};
    float lrow[2][2] = {{0.f, 0.f}, {0.f, 0.f}};

    const int brow = (lane & 7) + ((lane >> 4) << 3);
    const int bcx  = (lane >> 3) & 1;
    const int vrow = (lane & 7) + (((lane >> 3) & 1) << 3);
    const int vcx  = lane >> 4;

    const int nT = SEQ / 64;   // 32
    load_tile(0, 0);
    load_tile(1, 1);

    for (int it = 0; it < nT; it++) {
        if (it < nT - 1) asm volatile("cp.async.wait_group 1;" ::: "memory");
        else             asm volatile("cp.async.wait_group 0;" ::: "memory");
        __syncthreads();

        const int sb = it & 1;
        const uint32_t ksb = base + sb * ATILE;
        const uint32_t vsb = base + 2 * ATILE + sb * ATILE;

        // --- per sub-tile: S = Q K^T, online softmax, P -> smem ---
        #pragma unroll
        for (int s = 0; s < 2; s++) {
            float sacc[8][4];
            #pragma unroll
            for (int nt = 0; nt < 8; nt++)
                #pragma unroll
                for (int j = 0; j < 4; j++) sacc[nt][j] = 0.f;

            #pragma unroll
            for (int c2 = 0; c2 < 4; c2++) {
                uint32_t bf[8][2];
                #pragma unroll
                for (int np = 0; np < 4; np++) {
                    int row = np * 16 + brow;
                    uint32_t t[4];
                    ldsm4(t, ksb + SWOFF(row, 2 * c2 + bcx));
                    bf[2*np][0]   = t[0]; bf[2*np][1]   = t[1];
                    bf[2*np+1][0] = t[2]; bf[2*np+1][1] = t[3];
                }
                #pragma unroll
                for (int nt = 0; nt < 8; nt++)
                    mma16n8k16(sacc[nt], qf[s][c2], bf[nt]);
            }

            float tmax0 = -INFINITY, tmax1 = -INFINITY;
            #pragma unroll
            for (int nt = 0; nt < 8; nt++) {
                tmax0 = fmaxf(tmax0, fmaxf(sacc[nt][0], sacc[nt][1]));
                tmax1 = fmaxf(tmax1, fmaxf(sacc[nt][2], sacc[nt][3]));
            }
            tmax0 = fmaxf(tmax0, __shfl_xor_sync(0xffffffffu, tmax0, 1));
            tmax0 = fmaxf(tmax0, __shfl_xor_sync(0xffffffffu, tmax0, 2));
            tmax1 = fmaxf(tmax1, __shfl_xor_sync(0xffffffffu, tmax1, 1));
            tmax1 = fmaxf(tmax1, __shfl_xor_sync(0xffffffffu, tmax1, 2));

            const float mn0 = fmaxf(mrow[s][0], tmax0);
            const float mn1 = fmaxf(mrow[s][1], tmax1);
            const float sc0 = __expf(mrow[s][0] - mn0);
            const float sc1 = __expf(mrow[s][1] - mn1);
            mrow[s][0] = mn0; mrow[s][1] = mn1;

            float ps0 = 0.f, ps1 = 0.f;
            uint32_t* pr0 = Ps + (m0 + s*16 + g)     * ALD;
            uint32_t* pr1 = Ps + (m0 + s*16 + 8 + g) * ALD;
            #pragma unroll
            for (int nt = 0; nt < 8; nt++) {
                float p0 = __expf(sacc[nt][0] - mn0);
                float p1 = __expf(sacc[nt][1] - mn0);
                float p2 = __expf(sacc[nt][2] - mn1);
                float p3 = __expf(sacc[nt][3] - mn1);
                ps0 += p0 + p1; ps1 += p2 + p3;
                int pw = (nt >> 1) * 8 + 2*r + (nt & 1);
                pr0[pw] = h2(p0, p1);
                pr1[pw] = h2(p2, p3);
                oacc[s][nt][0] *= sc0; oacc[s][nt][1] *= sc0;
                oacc[s][nt][2] *= sc1; oacc[s][nt][3] *= sc1;
            }
            ps0 += __shfl_xor_sync(0xffffffffu, ps0, 1);
            ps0 += __shfl_xor_sync(0xffffffffu, ps0, 2);
            ps1 += __shfl_xor_sync(0xffffffffu, ps1, 1);
            ps1 += __shfl_xor_sync(0xffffffffu, ps1, 2);
            lrow[s][0] = lrow[s][0] * sc0 + ps0;
            lrow[s][1] = lrow[s][1] * sc1 + ps1;
        }

        __syncwarp();

        // --- O += P V : V B-frags via ldmatrix.trans, shared across sub-tiles
        #pragma unroll
        for (int c2 = 0; c2 < 4; c2++) {
            uint32_t vb[8][2];
            #pragma unroll
            for (int np = 0; np < 4; np++) {
                int row = 16 * c2 + vrow;
                uint32_t t[4];
                ldsm4t(t, vsb + SWOFF(row, 2 * np + vcx));
                vb[2*np][0]   = t[0]; vb[2*np][1]   = t[1];
                vb[2*np+1][0] = t[2]; vb[2*np+1][1] = t[3];
            }
            #pragma unroll
            for (int s = 0; s < 2; s++) {
                uint2 pa = *(const uint2*)&Ps[(m0 + s*16 + g)     * ALD + c2*8 + 2*r];
                uint2 pb = *(const uint2*)&Ps[(m0 + s*16 + 8 + g) * ALD + c2*8 + 2*r];
                uint32_t af[4];
                af[0] = pa.x; af[1] = pb.x; af[2] = pa.y; af[3] = pb.y;
                #pragma unroll
                for (int nt = 0; nt < 8; nt++)
                    mma16n8k16(oacc[s][nt], af, vb[nt]);
            }
        }

        __syncthreads();                     // all reads of buf sb complete
        if (it + 2 < nT) load_tile(it + 2, sb);
    }

    // epilogue: normalize, fp16 store
    #pragma unroll
    for (int s = 0; s < 2; s++) {
        const float inv0 = 1.f / lrow[s][0];
        const float inv1 = 1.f / lrow[s][1];
        __half* o0 = O + (size_t)(qbase + m0 + s*16 + g)     * DM + h * DH;
        __half* o1 = O + (size_t)(qbase + m0 + s*16 + 8 + g) * DM + h * DH;
        #pragma unroll
        for (int nt = 0; nt < 8; nt++) {
            *(uint32_t*)&o0[nt*8 + 2*r] = h2(oacc[s][nt][0] * inv0, oacc[s][nt][1] * inv0);
            *(uint32_t*)&o1[nt*8 + 2*r] = h2(oacc[s][nt][2] * inv1, oacc[s][nt][3] * inv1);
        }
    }
}

// ---------------- residual add + LayerNorm (optional fp16 copy) ------------
__global__ void __launch_bounds__(256) add_ln_kernel(
    const float* __restrict__ A, const float* __restrict__ B,
    const float* __restrict__ g, const float* __restrict__ be,
    float* __restrict__ out, __half* __restrict__ outh)
{
    const int row = blockIdx.x;
    const int c   = threadIdx.x * 4;

    float4 a = *(const float4*)&A[(size_t)row * DM + c];
    float4 b = *(const float4*)&B[(size_t)row * DM + c];
    float v0 = a.x + b.x, v1 = a.y + b.y, v2 = a.z + b.z, v3 = a.w + b.w;

    float s  = v0 + v1 + v2 + v3;
    float ss = v0*v0 + v1*v1 + v2*v2 + v3*v3;

    #pragma unroll
    for (int off = 16; off > 0; off >>= 1) {
        s  += __shfl_xor_sync(0xffffffffu, s,  off);
        ss += __shfl_xor_sync(0xffffffffu, ss, off);
    }
    __shared__ float rs[8], rss[8];
    const int warp = threadIdx.x >> 5, lane = threadIdx.x & 31;
    if (lane == 0) { rs[warp] = s; rss[warp] = ss; }
    __syncthreads();
    float st = 0.f, sst = 0.f;
    #pragma unroll
    for (int w = 0; w < 8; w++) { st += rs[w]; sst += rss[w]; }

    const float mu   = st  * (1.f / DM);
    const float var  = sst * (1.f / DM) - mu * mu;
    const float rstd = rsqrtf(var + EPSLN);

    float4 gg = *(const float4*)&g[c];
    float4 bb = *(const float4*)&be[c];
    float4 o;
    o.x = (v0 - mu) * rstd * gg.x + bb.x;
    o.y = (v1 - mu) * rstd * gg.y + bb.y;
    o.z = (v2 - mu) * rstd * gg.z + bb.z;
    o.w = (v3 - mu) * rstd * gg.w + bb.w;
    *(float4*)&out[(size_t)row * DM + c] = o;
    if (outh)
        *(uint2*)&outh[(size_t)row * DM + c] = make_uint2(h2(o.x, o.y), h2(o.z, o.w));
}

// ---------------- launch ----------------------------------------------------
extern "C" void kernel_launch(void* const* d_in, const int* in_sizes, int n_in,
                              void* d_out, int out_size)
{
    const float* x   = (const float*)d_in[0];
    const float* Wq  = (const float*)d_in[1];
    const float* bq  = (const float*)d_in[2];
    const float* Wk  = (const float*)d_in[3];
    const float* bk  = (const float*)d_in[4];
    const float* Wv  = (const float*)d_in[5];
    const float* bv  = (const float*)d_in[6];
    const float* Wo  = (const float*)d_in[7];
    const float* bo  = (const float*)d_in[8];
    const float* W1  = (const float*)d_in[9];
    const float* b1  = (const float*)d_in[10];
    const float* W2  = (const float*)d_in[11];
    const float* b2  = (const float*)d_in[12];
    const float* g1  = (const float*)d_in[13];
    const float* be1 = (const float*)d_in[14];
    const float* g2  = (const float*)d_in[15];
    const float* be2 = (const float*)d_in[16];
    float* out = (float*)d_out;

    float *p, *hbuf, *f2, *bqkv;
    __half *xh, *qkvh, *ah, *hh, *f1h, *wqkvh, *woh, *w1h, *w2h;
    cudaGetSymbolAddress((void**)&p,    gP);
    cudaGetSymbolAddress((void**)&hbuf, gH);
    cudaGetSymbolAddress((void**)&f2,   gF2);
    cudaGetSymbolAddress((void**)&bqkv, gBqkv);
    cudaGetSymbolAddress((void**)&xh,   hX);
    cudaGetSymbolAddress((void**)&qkvh, hQKV);
    cudaGetSymbolAddress((void**)&ah,   hA);
    cudaGetSymbolAddress((void**)&hh,   hH);
    cudaGetSymbolAddress((void**)&f1h,  hF1);
    cudaGetSymbolAddress((void**)&wqkvh,hWqkv);
    cudaGetSymbolAddress((void**)&woh,  hWo);
    cudaGetSymbolAddress((void**)&w1h,  hW1);
    cudaGetSymbolAddress((void**)&w2h,  hW2);

    cudaFuncSetAttribute(tc_gemm, cudaFuncAttributeMaxDynamicSharedMemorySize, GSMEM);
    cudaFuncSetAttribute(attn_tc, cudaFuncAttributeMaxDynamicSharedMemorySize, ATT_SMEM);

    // prepass
    f2h_kernel<<<MTOK*DM/2048, 256>>>(x,  xh);
    packw_kernel<<<DM*DM/1024, 256>>>(Wq, Wk, Wv, wqkvh);
    packb_kernel<<<3, 1024>>>(bq, bk, bv, bqkv);
    f2h_kernel<<<DM*DM/2048,  256>>>(Wo, woh);
    f2h_kernel<<<DFF*DM/2048, 256>>>(W1, w1h);
    f2h_kernel<<<DM*DFF/2048, 256>>>(W2, w2h);

    dim3 gQKV(QKVS / GBN, MTOK / GBM);   // (24, 32)
    dim3 gProj(DM / GBN,  MTOK / GBM);   // (8, 32)
    dim3 gFF1 (DFF / GBN, MTOK / GBM);   // (32, 32)

    tc_gemm<<<gQKV, 256, GSMEM>>>(xh, wqkvh, bqkv, nullptr, qkvh, MTOK, QKVS, DM, 0);

    attn_tc<<<dim3(SEQ / 128, NH, BATCH), 128, ATT_SMEM>>>(qkvh, ah);

    tc_gemm<<<gProj, 256, GSMEM>>>(ah, woh, bo, p, nullptr, MTOK, DM, DM, 0);
    add_ln_kernel<<<MTOK, 256>>>(x, p, g1, be1, hbuf, hh);

    tc_gemm<<<gFF1, 256, GSMEM>>>(hh, w1h, b1, nullptr, f1h, MTOK, DFF, DM, 1);
    tc_gemm<<<gProj, 256, GSMEM>>>(f1h, w2h, b2, f2, nullptr, MTOK, DM, DFF, 0);
    add_ln_kernel<<<MTOK, 256>>>(hbuf, f2, g2, be2, out, nullptr);
}

// round 16
// speedup vs baseline: 11.4702x; 1.0190x over previous
#include <cuda_runtime.h>
#include <cuda_fp16.h>
#include <cstdint>
#include <math.h>

#define DM    1024
#define DFF   4096
#define NH    16
#define DH    64
#define BATCH 2
#define SEQ   2048
#define MTOK  (BATCH*SEQ)   // 4096 tokens
#define QKVS  3072          // packed qkv row stride
#define EPSLN 1e-5f

// ---------------- scratch (device globals; no allocation allowed) ----------
__device__ float  gP [MTOK*DM];     // attn out-proj (fp32)
__device__ float  gH [MTOK*DM];     // after LN1 (fp32, residual for LN2)
__device__ float  gF2[MTOK*DM];     // FFN out (fp32)
__device__ float  gBqkv[QKVS];      // packed bias (bq*0.125, bk, bv)
__device__ __half hX  [MTOK*DM];
__device__ __half hQKV[MTOK*QKVS];  // packed q|k|v
__device__ __half hA  [MTOK*DM];
__device__ __half hH  [MTOK*DM];
__device__ __half hF1 [MTOK*DFF];
__device__ __half hWqkv[QKVS*DM];   // packed Wq*0.125|Wk|Wv
__device__ __half hWo[DM*DM];
__device__ __half hW1[DFF*DM];
__device__ __half hW2[DM*DFF];

// ======================= helpers ===========================================
__device__ __forceinline__ uint32_t scast(const void* p) {
    return (uint32_t)__cvta_generic_to_shared(p);
}
__device__ __forceinline__ void cp16(uint32_t dst, const void* src) {
    asm volatile("cp.async.cg.shared.global [%0], [%1], 16;" :: "r"(dst), "l"(src));
}
__device__ __forceinline__ void cp_commit() {
    asm volatile("cp.async.commit_group;" ::: "memory");
}
__device__ __forceinline__ void ldsm4(uint32_t* d, uint32_t a) {
    asm volatile("ldmatrix.sync.aligned.m8n8.x4.shared.b16 {%0,%1,%2,%3}, [%4];"
                 : "=r"(d[0]), "=r"(d[1]), "=r"(d[2]), "=r"(d[3]) : "r"(a));
}
__device__ __forceinline__ void ldsm4t(uint32_t* d, uint32_t a) {
    asm volatile("ldmatrix.sync.aligned.m8n8.x4.trans.shared.b16 {%0,%1,%2,%3}, [%4];"
                 : "=r"(d[0]), "=r"(d[1]), "=r"(d[2]), "=r"(d[3]) : "r"(a));
}
__device__ __forceinline__ uint32_t h2(float a, float b) {
    __half2 v = __floats2half2_rn(a, b);
    return *(uint32_t*)&v;
}
__device__ __forceinline__ void mma16n8k16(float* c, const uint32_t* a, const uint32_t* b) {
    asm volatile(
        "mma.sync.aligned.m16n8k16.row.col.f32.f16.f16.f32 "
        "{%0,%1,%2,%3}, {%4,%5,%6,%7}, {%8,%9}, {%0,%1,%2,%3};"
        : "+f"(c[0]), "+f"(c[1]), "+f"(c[2]), "+f"(c[3])
        : "r"(a[0]), "r"(a[1]), "r"(a[2]), "r"(a[3]), "r"(b[0]), "r"(b[1]));
}

// tile rows are 64 halves = 128B = 8 chunks of 16B; chunk swizzle: c ^ (row&7)
#define SWOFF(row, c) ((row) * 128 + (((c) ^ ((row) & 7)) << 4))

// ---------------- merged prepass -------------------------------------------
// one launch: x, Wq*0.125|Wk|Wv pack, Wo, W1, W2 (fp32->fp16), packed bias.
// block = 2048 elems (256 thr x 8); segment dispatch by blockIdx range.
__global__ void __launch_bounds__(256) prep_kernel(
    const float* __restrict__ x,
    const float* __restrict__ Wq, const float* __restrict__ Wk,
    const float* __restrict__ Wv, const float* __restrict__ Wo,
    const float* __restrict__ W1, const float* __restrict__ W2,
    const float* __restrict__ bq, const float* __restrict__ bk,
    const float* __restrict__ bv,
    __half* __restrict__ xh, __half* __restrict__ wqkvh,
    __half* __restrict__ woh, __half* __restrict__ w1h,
    __half* __restrict__ w2h, float* __restrict__ bqkv)
{
    int bid = blockIdx.x;
    if (bid >= 8192) {   // bias segment: 3 blocks x 1024 elems
        int seg = bid - 8192;
        int i = threadIdx.x * 4;
        const float* src = (seg == 0) ? bq : (seg == 1) ? bk : bv;
        float sc = (seg == 0) ? 0.125f : 1.f;
        float4 v = *(const float4*)&src[i];
        float4 o = make_float4(v.x * sc, v.y * sc, v.z * sc, v.w * sc);
        *(float4*)&bqkv[seg * DM + i] = o;
        return;
    }
    const float* in; __half* out; float sc = 1.f;
    if      (bid < 2048) { in = x;  out = xh; }
    else if (bid < 2560) { in = Wq; out = wqkvh;             bid -= 2048; sc = 0.125f; }
    else if (bid < 3072) { in = Wk; out = wqkvh + DM*DM;     bid -= 2560; }
    else if (bid < 3584) { in = Wv; out = wqkvh + 2*DM*DM;   bid -= 3072; }
    else if (bid < 4096) { in = Wo; out = woh;               bid -= 3584; }
    else if (bid < 6144) { in = W1; out = w1h;               bid -= 4096; }
    else                 { in = W2; out = w2h;               bid -= 6144; }
    int i = (bid * 256 + threadIdx.x) * 8;
    float4 v0 = *(const float4*)&in[i];
    float4 v1 = *(const float4*)&in[i + 4];
    *(uint4*)&out[i] = make_uint4(h2(v0.x*sc, v0.y*sc), h2(v0.z*sc, v0.w*sc),
                                  h2(v1.x*sc, v1.y*sc), h2(v1.z*sc, v1.w*sc));
}

// ======================= fp16 3-stage cp.async GEMM ========================
// C = A[M,K] @ W[N,K]^T + bias; optional ReLU; fp32 and/or fp16 out.
// Block 128x128, 256 thr = 8 warps (2M x 4N), warp tile 64x32, BK=64, 3 stages.
// ONE __syncthreads per k-iter (next iter's sync protects buffer reuse).
#define GBM 128
#define GBN 128
#define GBK 64
#define GSTAGE (128*128)          // 16KB per matrix per stage
#define GSMEM  (6*GSTAGE)         // 96KB

__global__ void __launch_bounds__(256, 2) tc_gemm(
    const __half* __restrict__ A, const __half* __restrict__ W,
    const float* __restrict__ bias, float* __restrict__ Cf, __half* __restrict__ Ch,
    int M, int N, int K, int doRelu)
{
    extern __shared__ char smem[];
    const int tid  = threadIdx.x;
    const int wid  = tid >> 5;
    const int lane = tid & 31;
    const int g    = lane >> 2;
    const int r    = lane & 3;
    const int warpM = wid >> 2;
    const int warpN = wid & 3;
    const int bm = blockIdx.y * GBM;
    const int bn = blockIdx.x * GBN;

    const int lrow = tid >> 1;
    const int lc0  = (tid & 1) * 4;
    const __half* agp = &A[(size_t)(bm + lrow) * K + lc0 * 8];
    const __half* wgp = &W[(size_t)(bn + lrow) * K + lc0 * 8];

    const int arow = lane & 15;
    const int acx  = lane >> 4;
    const int brow = (lane & 7) + ((lane >> 4) << 3);
    const int bcx  = (lane >> 3) & 1;

    float acc[4][4][4];
    #pragma unroll
    for (int mi = 0; mi < 4; mi++)
        #pragma unroll
        for (int ni = 0; ni < 4; ni++)
            #pragma unroll
            for (int j = 0; j < 4; j++) acc[mi][ni][j] = 0.f;

    const int nIter = K / GBK;

    auto load_stage = [&](int it) {
        int s  = it - (it / 3) * 3;
        int k0 = it * GBK;
        uint32_t da = scast(smem + s * GSTAGE) + lrow * 128;
        uint32_t db = scast(smem + (3 + s) * GSTAGE) + lrow * 128;
        #pragma unroll
        for (int c = 0; c < 4; c++) {
            int ch = lc0 + c;
            cp16(da + ((ch ^ (lrow & 7)) << 4), agp + k0 + c * 8);
            cp16(db + ((ch ^ (lrow & 7)) << 4), wgp + k0 + c * 8);
        }
        cp_commit();
    };

    load_stage(0);
    load_stage(1);

    for (int it = 0; it < nIter; it++) {
        if (it < nIter - 1) asm volatile("cp.async.wait_group 1;" ::: "memory");
        else                asm volatile("cp.async.wait_group 0;" ::: "memory");
        __syncthreads();   // also proves compute(it-1) done -> buf (it+2)%3 idle
        if (it + 2 < nIter) load_stage(it + 2);

        int s = it - (it / 3) * 3;
        const uint32_t abase = scast(smem + s * GSTAGE);
        const uint32_t bbase = scast(smem + (3 + s) * GSTAGE);

        #pragma unroll
        for (int c2 = 0; c2 < 4; c2++) {
            uint32_t af[4][4], bf[4][2];
            #pragma unroll
            for (int mi = 0; mi < 4; mi++) {
                int row = warpM * 64 + mi * 16 + arow;
                ldsm4(af[mi], abase + SWOFF(row, 2 * c2 + acx));
            }
            #pragma unroll
            for (int p = 0; p < 2; p++) {
                int row = warpN * 32 + p * 16 + brow;
                uint32_t t[4];
                ldsm4(t, bbase + SWOFF(row, 2 * c2 + bcx));
                bf[2*p][0]   = t[0]; bf[2*p][1]   = t[1];
                bf[2*p+1][0] = t[2]; bf[2*p+1][1] = t[3];
            }
            #pragma unroll
            for (int mi = 0; mi < 4; mi++)
                #pragma unroll
                for (int ni = 0; ni < 4; ni++)
                    mma16n8k16(acc[mi][ni], af[mi], bf[ni]);
        }
    }

    #pragma unroll
    for (int ni = 0; ni < 4; ni++) {
        int col = bn + warpN * 32 + ni * 8 + 2 * r;
        float bx = bias[col], by = bias[col + 1];
        #pragma unroll
        for (int mi = 0; mi < 4; mi++) {
            int row0 = bm + warpM * 64 + mi * 16 + g;
            float2 v0, v1;
            v0.x = acc[mi][ni][0] + bx; v0.y = acc[mi][ni][1] + by;
            v1.x = acc[mi][ni][2] + bx; v1.y = acc[mi][ni][3] + by;
            if (doRelu) {
                v0.x = fmaxf(v0.x, 0.f); v0.y = fmaxf(v0.y, 0.f);
                v1.x = fmaxf(v1.x, 0.f); v1.y = fmaxf(v1.y, 0.f);
            }
            if (Cf) {
                *(float2*)&Cf[(size_t)row0 * N + col]       = v0;
                *(float2*)&Cf[(size_t)(row0 + 8) * N + col] = v1;
            }
            if (Ch) {
                *(uint32_t*)&Ch[(size_t)row0 * N + col]       = h2(v0.x, v0.y);
                *(uint32_t*)&Ch[(size_t)(row0 + 8) * N + col] = h2(v1.x, v1.y);
            }
        }
    }
}

// ======================= fp16 flash attention ==============================
// Block: 128 q-rows of one (b,h). 128 thr = 4 warps, 32 q-rows (2 sub-tiles).
// 128-key K/V tiles (two 64-key inner halves), double-buffered.
// Dynamic smem: K[2][16KB], V[2][16KB], Ps[20KB] = 86016 B -> 2 CTAs/SM.
#define ALD 40
#define ATILE 16384
#define ATT_SMEM (4*ATILE + 128*ALD*4)

__global__ void __launch_bounds__(128) attn_tc(
    const __half* __restrict__ QKV, __half* __restrict__ O)
{
    extern __shared__ char smem[];
    const uint32_t base = scast(smem);
    uint32_t* Ps = (uint32_t*)(smem + 4*ATILE);

    const int h = blockIdx.y;
    const int b = blockIdx.z;
    const int qbase = b * SEQ + blockIdx.x * 128;
    const int tid  = threadIdx.x;
    const int wid  = tid >> 5;
    const int lane = tid & 31;
    const int g    = lane >> 2;
    const int r    = lane & 3;
    const int m0   = wid * 32;

    // tile loader: 128 keys of K+V for tile t into buffer s (one commit group)
    auto load_tile = [&](int t, int s) {
        uint32_t kd = base + s * ATILE;
        uint32_t vd = base + 2 * ATILE + s * ATILE;
        #pragma unroll
        for (int i = 0; i < 8; i++) {
            int idx = tid + i * 128;
            int row = idx >> 3;       // key 0..127
            int c   = idx & 7;
            const size_t rb = (size_t)(b * SEQ + t * 128 + row) * QKVS + h * DH + c * 8;
            cp16(kd + SWOFF(row, c), QKV + rb + DM);      // K section
            cp16(vd + SWOFF(row, c), QKV + rb + 2 * DM);  // V section
        }
        cp_commit();
    };

    // Q fragments (1/sqrt(64) folded into Wq/bq)
    uint32_t qf[2][4][4];
    #pragma unroll
    for (int s = 0; s < 2; s++) {
        const __half* q0 = QKV + (size_t)(qbase + m0 + s*16 + g)     * QKVS + h * DH;
        const __half* q1 = QKV + (size_t)(qbase + m0 + s*16 + 8 + g) * QKVS + h * DH;
        #pragma unroll
        for (int c = 0; c < 4; c++) {
            qf[s][c][0] = *(const uint32_t*)&q0[c*16 + 2*r];
            qf[s][c][1] = *(const uint32_t*)&q1[c*16 + 2*r];
            qf[s][c][2] = *(const uint32_t*)&q0[c*16 + 8 + 2*r];
            qf[s][c][3] = *(const uint32_t*)&q1[c*16 + 8 + 2*r];
        }
    }

    float oacc[2][8][4];
    #pragma unroll
    for (int s = 0; s < 2; s++)
        #pragma unroll
        for (int nt = 0; nt < 8; nt++)
            #pragma unroll
            for (int j = 0; j < 4; j++) oacc[s][nt][j] = 0.f;
    float mrow[2][2] = {{-INFINITY, -INFINITY}, {-INFINITY, -INFINITY}};
    float lrow[2][2] = {{0.f, 0.f}, {0.f, 0.f}};

    const int brow = (lane & 7) + ((lane >> 4) << 3);
    const int bcx  = (lane >> 3) & 1;
    const int vrow = (lane & 7) + (((lane >> 3) & 1) << 3);
    const int vcx  = lane >> 4;

    const int nT = SEQ / 128;   // 16
    load_tile(0, 0);
    load_tile(1, 1);

    for (int it = 0; it < nT; it++) {
        if (it < nT - 1) asm volatile("cp.async.wait_group 1;" ::: "memory");
        else             asm volatile("cp.async.wait_group 0;" ::: "memory");
        __syncthreads();

        const int sb = it & 1;

        #pragma unroll
        for (int half = 0; half < 2; half++) {
            const uint32_t ksb = base + sb * ATILE + half * 8192;
            const uint32_t vsb = base + 2 * ATILE + sb * ATILE + half * 8192;

            // --- per sub-tile: S = Q K^T, online softmax, P -> smem ---
            #pragma unroll
            for (int s = 0; s < 2; s++) {
                float sacc[8][4];
                #pragma unroll
                for (int nt = 0; nt < 8; nt++)
                    #pragma unroll
                    for (int j = 0; j < 4; j++) sacc[nt][j] = 0.f;

                #pragma unroll
                for (int c2 = 0; c2 < 4; c2++) {
                    uint32_t bf[8][2];
                    #pragma unroll
                    for (int np = 0; np < 4; np++) {
                        int row = np * 16 + brow;
                        uint32_t t[4];
                        ldsm4(t, ksb + SWOFF(row, 2 * c2 + bcx));
                        bf[2*np][0]   = t[0]; bf[2*np][1]   = t[1];
                        bf[2*np+1][0] = t[2]; bf[2*np+1][1] = t[3];
                    }
                    #pragma unroll
                    for (int nt = 0; nt < 8; nt++)
                        mma16n8k16(sacc[nt], qf[s][c2], bf[nt]);
                }

                float tmax0 = -INFINITY, tmax1 = -INFINITY;
                #pragma unroll
                for (int nt = 0; nt < 8; nt++) {
                    tmax0 = fmaxf(tmax0, fmaxf(sacc[nt][0], sacc[nt][1]));
                    tmax1 = fmaxf(tmax1, fmaxf(sacc[nt][2], sacc[nt][3]));
                }
                tmax0 = fmaxf(tmax0, __shfl_xor_sync(0xffffffffu, tmax0, 1));
                tmax0 = fmaxf(tmax0, __shfl_xor_sync(0xffffffffu, tmax0, 2));
                tmax1 = fmaxf(tmax1, __shfl_xor_sync(0xffffffffu, tmax1, 1));
                tmax1 = fmaxf(tmax1, __shfl_xor_sync(0xffffffffu, tmax1, 2));

                const float mn0 = fmaxf(mrow[s][0], tmax0);
                const float mn1 = fmaxf(mrow[s][1], tmax1);
                const float sc0 = __expf(mrow[s][0] - mn0);
                const float sc1 = __expf(mrow[s][1] - mn1);
                mrow[s][0] = mn0; mrow[s][1] = mn1;

                float ps0 = 0.f, ps1 = 0.f;
                uint32_t* pr0 = Ps + (m0 + s*16 + g)     * ALD;
                uint32_t* pr1 = Ps + (m0 + s*16 + 8 + g) * ALD;
                #pragma unroll
                for (int nt = 0; nt < 8; nt++) {
                    float p0 = __expf(sacc[nt][0] - mn0);
                    float p1 = __expf(sacc[nt][1] - mn0);
                    float p2 = __expf(sacc[nt][2] - mn1);
                    float p3 = __expf(sacc[nt][3] - mn1);
                    ps0 += p0 + p1; ps1 += p2 + p3;
                    int pw = (nt >> 1) * 8 + 2*r + (nt & 1);
                    pr0[pw] = h2(p0, p1);
                    pr1[pw] = h2(p2, p3);
                    oacc[s][nt][0] *= sc0; oacc[s][nt][1] *= sc0;
                    oacc[s][nt][2] *= sc1; oacc[s][nt][3] *= sc1;
                }
                ps0 += __shfl_xor_sync(0xffffffffu, ps0, 1);
                ps0 += __shfl_xor_sync(0xffffffffu, ps0, 2);
                ps1 += __shfl_xor_sync(0xffffffffu, ps1, 1);
                ps1 += __shfl_xor_sync(0xffffffffu, ps1, 2);
                lrow[s][0] = lrow[s][0] * sc0 + ps0;
                lrow[s][1] = lrow[s][1] * sc1 + ps1;
            }

            __syncwarp();   // warp reads only its own 32 Ps rows

            // --- O += P V : V B-frags via ldmatrix.trans, shared across sub-tiles
            #pragma unroll
            for (int c2 = 0; c2 < 4; c2++) {
                uint32_t vb[8][2];
                #pragma unroll
                for (int np = 0; np < 4; np++) {
                    int row = 16 * c2 + vrow;
                    uint32_t t[4];
                    ldsm4t(t, vsb + SWOFF(row, 2 * np + vcx));
                    vb[2*np][0]   = t[0]; vb[2*np][1]   = t[1];
                    vb[2*np+1][0] = t[2]; vb[2*np+1][1] = t[3];
                }
                #pragma unroll
                for (int s = 0; s < 2; s++) {
                    uint2 pa = *(const uint2*)&Ps[(m0 + s*16 + g)     * ALD + c2*8 + 2*r];
                    uint2 pb = *(const uint2*)&Ps[(m0 + s*16 + 8 + g) * ALD + c2*8 + 2*r];
                    uint32_t af[4];
                    af[0] = pa.x; af[1] = pb.x; af[2] = pa.y; af[3] = pb.y;
                    #pragma unroll
                    for (int nt = 0; nt < 8; nt++)
                        mma16n8k16(oacc[s][nt], af, vb[nt]);
                }
            }
            __syncwarp();   // Ps reads done before next half rewrites
        }

        __syncthreads();                     // all reads of buf sb complete
        if (it + 2 < nT) load_tile(it + 2, sb);
    }

    // epilogue: normalize, fp16 store
    #pragma unroll
    for (int s = 0; s < 2; s++) {
        const float inv0 = 1.f / lrow[s][0];
        const float inv1 = 1.f / lrow[s][1];
        __half* o0 = O + (size_t)(qbase + m0 + s*16 + g)     * DM + h * DH;
        __half* o1 = O + (size_t)(qbase + m0 + s*16 + 8 + g) * DM + h * DH;
        #pragma unroll
        for (int nt = 0; nt < 8; nt++) {
            *(uint32_t*)&o0[nt*8 + 2*r] = h2(oacc[s][nt][0] * inv0, oacc[s][nt][1] * inv0);
            *(uint32_t*)&o1[nt*8 + 2*r] = h2(oacc[s][nt][2] * inv1, oacc[s][nt][3] * inv1);
        }
    }
}

// ---------------- residual add + LayerNorm (optional fp16 copy) ------------
__global__ void __launch_bounds__(256) add_ln_kernel(
    const float* __restrict__ A, const float* __restrict__ B,
    const float* __restrict__ g, const float* __restrict__ be,
    float* __restrict__ out, __half* __restrict__ outh)
{
    const int row = blockIdx.x;
    const int c   = threadIdx.x * 4;

    float4 a = *(const float4*)&A[(size_t)row * DM + c];
    float4 b = *(const float4*)&B[(size_t)row * DM + c];
    float v0 = a.x + b.x, v1 = a.y + b.y, v2 = a.z + b.z, v3 = a.w + b.w;

    float s  = v0 + v1 + v2 + v3;
    float ss = v0*v0 + v1*v1 + v2*v2 + v3*v3;

    #pragma unroll
    for (int off = 16; off > 0; off >>= 1) {
        s  += __shfl_xor_sync(0xffffffffu, s,  off);
        ss += __shfl_xor_sync(0xffffffffu, ss, off);
    }
    __shared__ float rs[8], rss[8];
    const int warp = threadIdx.x >> 5, lane = threadIdx.x & 31;
    if (lane == 0) { rs[warp] = s; rss[warp] = ss; }
    __syncthreads();
    float st = 0.f, sst = 0.f;
    #pragma unroll
    for (int w = 0; w < 8; w++) { st += rs[w]; sst += rss[w]; }

    const float mu   = st  * (1.f / DM);
    const float var  = sst * (1.f / DM) - mu * mu;
    const float rstd = rsqrtf(var + EPSLN);

    float4 gg = *(const float4*)&g[c];
    float4 bb = *(const float4*)&be[c];
    float4 o;
    o.x = (v0 - mu) * rstd * gg.x + bb.x;
    o.y = (v1 - mu) * rstd * gg.y + bb.y;
    o.z = (v2 - mu) * rstd * gg.z + bb.z;
    o.w = (v3 - mu) * rstd * gg.w + bb.w;
    *(float4*)&out[(size_t)row * DM + c] = o;
    if (outh)
        *(uint2*)&outh[(size_t)row * DM + c] = make_uint2(h2(o.x, o.y), h2(o.z, o.w));
}

// ---------------- launch ----------------------------------------------------
extern "C" void kernel_launch(void* const* d_in, const int* in_sizes, int n_in,
                              void* d_out, int out_size)
{
    const float* x   = (const float*)d_in[0];
    const float* Wq  = (const float*)d_in[1];
    const float* bq  = (const float*)d_in[2];
    const float* Wk  = (const float*)d_in[3];
    const float* bk  = (const float*)d_in[4];
    const float* Wv  = (const float*)d_in[5];
    const float* bv  = (const float*)d_in[6];
    const float* Wo  = (const float*)d_in[7];
    const float* bo  = (const float*)d_in[8];
    const float* W1  = (const float*)d_in[9];
    const float* b1  = (const float*)d_in[10];
    const float* W2  = (const float*)d_in[11];
    const float* b2  = (const float*)d_in[12];
    const float* g1  = (const float*)d_in[13];
    const float* be1 = (const float*)d_in[14];
    const float* g2  = (const float*)d_in[15];
    const float* be2 = (const float*)d_in[16];
    float* out = (float*)d_out;

    float *p, *hbuf, *f2, *bqkv;
    __half *xh, *qkvh, *ah, *hh, *f1h, *wqkvh, *woh, *w1h, *w2h;
    cudaGetSymbolAddress((void**)&p,    gP);
    cudaGetSymbolAddress((void**)&hbuf, gH);
    cudaGetSymbolAddress((void**)&f2,   gF2);
    cudaGetSymbolAddress((void**)&bqkv, gBqkv);
    cudaGetSymbolAddress((void**)&xh,   hX);
    cudaGetSymbolAddress((void**)&qkvh, hQKV);
    cudaGetSymbolAddress((void**)&ah,   hA);
    cudaGetSymbolAddress((void**)&hh,   hH);
    cudaGetSymbolAddress((void**)&f1h,  hF1);
    cudaGetSymbolAddress((void**)&wqkvh,hWqkv);
    cudaGetSymbolAddress((void**)&woh,  hWo);
    cudaGetSymbolAddress((void**)&w1h,  hW1);
    cudaGetSymbolAddress((void**)&w2h,  hW2);

    cudaFuncSetAttribute(tc_gemm, cudaFuncAttributeMaxDynamicSharedMemorySize, GSMEM);
    cudaFuncSetAttribute(attn_tc, cudaFuncAttributeMaxDynamicSharedMemorySize, ATT_SMEM);

    // merged prepass: one launch
    prep_kernel<<<8195, 256>>>(x, Wq, Wk, Wv, Wo, W1, W2, bq, bk, bv,
                               xh, wqkvh, woh, w1h, w2h, bqkv);

    dim3 gQKV(QKVS / GBN, MTOK / GBM);   // (24, 32)
    dim3 gProj(DM / GBN,  MTOK / GBM);   // (8, 32)
    dim3 gFF1 (DFF / GBN, MTOK / GBM);   // (32, 32)

    tc_gemm<<<gQKV, 256, GSMEM>>>(xh, wqkvh, bqkv, nullptr, qkvh, MTOK, QKVS, DM, 0);

    attn_tc<<<dim3(SEQ / 128, NH, BATCH), 128, ATT_SMEM>>>(qkvh, ah);

    tc_gemm<<<gProj, 256, GSMEM>>>(ah, woh, bo, p, nullptr, MTOK, DM, DM, 0);
    add_ln_kernel<<<MTOK, 256>>>(x, p, g1, be1, hbuf, hh);

    tc_gemm<<<gFF1, 256, GSMEM>>>(hh, w1h, b1, nullptr, f1h, MTOK, DFF, DM, 1);
    tc_gemm<<<gProj, 256, GSMEM>>>(f1h, w2h, b2, f2, nullptr, MTOK, DM, DFF, 0);
    add_ln_kernel<<<MTOK, 256>>>(hbuf, f2, g2, be2, out, nullptr);
}